// round 3
// baseline (speedup 1.0000x reference)
#include <cuda_runtime.h>
#include <math.h>

#define HLR   96
#define HWLR  9216
#define HHR   384
#define NQ    147456

// ---------------- static device scratch (no allocation allowed) ----------------
__device__ float g_b1[64*HWLR];      // conv1 out (relu)
__device__ float g_b2[64*HWLR];      // conv2 out (relu)
__device__ float g_feat[64*HWLR];    // conv3 out (no relu)
__device__ float g_offH[16*256];     // heavy layer1 offsets per sub-position
__device__ float g_offC[16*64];      // classifier layer1 offsets
__device__ float g_offL[16*64];      // light layer1 offsets
__device__ float g_pred[3*NQ];       // pre-refinement prediction, CHW
__device__ int   g_flag[NQ];         // hard/easy map

// ---------------- offset precompute ----------------
__global__ void precompute_kernel(const float* __restrict__ wh1, const float* __restrict__ bh1,
                                  const float* __restrict__ wc1, const float* __restrict__ bc1,
                                  const float* __restrict__ wl1, const float* __restrict__ bl1,
                                  const float* __restrict__ cell)
{
    int t = threadIdx.x;
    float rcy = cell[0]*96.0f, rcx = cell[1]*96.0f;
    float rel[4];
#pragma unroll
    for (int m=0;m<4;m++){
        float cy = -1.0f + (2.0f*(float)m + 1.0f)/384.0f;   // HR coord, iy=0 for m<4
        float fy = -1.0f + 1.0f/96.0f;                       // LR pixel-0 center
        rel[m] = (cy - fy)*96.0f;                            // = {-0.75,-0.25,0.25,0.75}
    }
    for (int m=0;m<16;m++){
        float ry = rel[m>>2], rx = rel[m&3];
        g_offH[m*256+t] = ry*wh1[64*256+t] + rx*wh1[65*256+t]
                        + rcy*wh1[66*256+t] + rcx*wh1[67*256+t] + bh1[t];
        if (t < 64){
            g_offC[m*64+t] = ry*wc1[64*64+t] + rx*wc1[65*64+t]
                           + rcy*wc1[66*64+t] + rcx*wc1[67*64+t] + bc1[t];
            g_offL[m*64+t] = ry*wl1[64*64+t] + rx*wl1[65*64+t]
                           + rcy*wl1[66*64+t] + rcx*wl1[67*64+t] + bl1[t];
        }
    }
}

// ---------------- 3x3 SAME conv, 64 output channels ----------------
// grid = 96 rows; block = 256 threads; thread computes 4 oc x 6 x.
template<int IC, bool RELU>
__global__ __launch_bounds__(256) void conv3x3_kernel(
    const float* __restrict__ in, const float* __restrict__ w,
    const float* __restrict__ bias, float* __restrict__ out)
{
    constexpr int CH = (IC < 16) ? IC : 16;
    __shared__ float sIn[CH][3][100];
    const int y   = blockIdx.x;
    const int tid = threadIdx.x;
    const int oc0 = (tid >> 4) * 4;
    const int x0  = (tid & 15) * 6;
    float acc[4][6];
#pragma unroll
    for (int i=0;i<4;i++)
#pragma unroll
        for (int j=0;j<6;j++) acc[i][j]=0.0f;

    for (int c0=0;c0<IC;c0+=CH){
        __syncthreads();
        for (int idx=tid; idx<CH*3*96; idx+=256){
            int ic = idx/288;
            int rem = idx - ic*288;
            int ry = rem/96;
            int x  = rem - ry*96;
            int yy = y + ry - 1;
            float v = 0.0f;
            if (yy>=0 && yy<96) v = in[(c0+ic)*HWLR + yy*96 + x];
            sIn[ic][ry][x+1] = v;
        }
        for (int idx=tid; idx<CH*3; idx+=256){
            int ic = idx/3, ry = idx-ic*3;
            sIn[ic][ry][0]  = 0.0f;
            sIn[ic][ry][97] = 0.0f;
        }
        __syncthreads();
#pragma unroll 2
        for (int ic=0; ic<CH; ic++){
            float r0[8],r1[8],r2[8];
#pragma unroll
            for (int d=0;d<8;d++){
                r0[d]=sIn[ic][0][x0+d];
                r1[d]=sIn[ic][1][x0+d];
                r2[d]=sIn[ic][2][x0+d];
            }
#pragma unroll
            for (int i=0;i<4;i++){
                const float* wp = w + ((oc0+i)*IC + (c0+ic))*9;
                float w00=__ldg(wp+0), w01=__ldg(wp+1), w02=__ldg(wp+2);
                float w10=__ldg(wp+3), w11=__ldg(wp+4), w12=__ldg(wp+5);
                float w20=__ldg(wp+6), w21=__ldg(wp+7), w22=__ldg(wp+8);
#pragma unroll
                for (int j=0;j<6;j++){
                    acc[i][j] += w00*r0[j]+w01*r0[j+1]+w02*r0[j+2]
                               + w10*r1[j]+w11*r1[j+1]+w12*r1[j+2]
                               + w20*r2[j]+w21*r2[j+1]+w22*r2[j+2];
                }
            }
        }
    }
#pragma unroll
    for (int i=0;i<4;i++){
        float b = __ldg(bias+oc0+i);
#pragma unroll
        for (int j=0;j<6;j++){
            float v = acc[i][j]+b;
            if (RELU) v = fmaxf(v,0.0f);
            out[(oc0+i)*HWLR + y*96 + x0 + j] = v;
        }
    }
}

// ---------------- dense 256x256 layer over R compacted query rows ----------------
template<int R>
__device__ __forceinline__ void dense_layer(const float (*in)[256], float (*outp)[256],
    const float* __restrict__ W, const float* __restrict__ bias, int tid)
{
    float acc[R];
#pragma unroll
    for (int i=0;i<R;i++) acc[i]=0.0f;
#pragma unroll 2
    for (int k=0;k<256;k+=4){
        float w0=__ldg(&W[(k+0)*256+tid]);
        float w1=__ldg(&W[(k+1)*256+tid]);
        float w2=__ldg(&W[(k+2)*256+tid]);
        float w3=__ldg(&W[(k+3)*256+tid]);
#pragma unroll
        for (int i=0;i<R;i++){
            float4 h = *(const float4*)(&in[i][k]);     // uniform -> smem broadcast
            acc[i] += w0*h.x + w1*h.y + w2*h.z + w3*h.w;
        }
    }
    float b = __ldg(&bias[tid]);
#pragma unroll
    for (int i=0;i<R;i++) outp[i][tid] = fmaxf(acc[i]+b, 0.0f);
}

template<int R>
__device__ __forceinline__ void heavy23(float (*sA)[256], float (*sB)[256],
    const float* __restrict__ wh2, const float* __restrict__ bh2,
    const float* __restrict__ wh3, const float* __restrict__ bh3, int tid)
{
    dense_layer<R>(sA, sB, wh2, bh2, tid);
    __syncthreads();
    dense_layer<R>(sB, sA, wh3, bh3, tid);
    __syncthreads();
}

// ---------------- main per-LR-pixel kernel: classifier + light + compacted heavy ----------------
__global__ __launch_bounds__(256) void mlp_kernel(
    const float* __restrict__ lr,
    const float* __restrict__ wh1, const float* __restrict__ wh2, const float* __restrict__ bh2,
    const float* __restrict__ wh3, const float* __restrict__ bh3,
    const float* __restrict__ wh4, const float* __restrict__ bh4,
    const float* __restrict__ wc1, const float* __restrict__ wc2, const float* __restrict__ bc2,
    const float* __restrict__ wl1, const float* __restrict__ wl2, const float* __restrict__ bl2,
    float* __restrict__ out, int out_size)
{
    __shared__ float sfeat[64];
    __shared__ float sA[16][256];
    __shared__ float sB[16][256];
    __shared__ float sCc[64];
    __shared__ float sLl[64];
    __shared__ float sPredL[16][3];
    __shared__ float sPredH[16][3];
    __shared__ int sFlag[16];
    __shared__ int sMlist[16];
    __shared__ int sInv[16];
    __shared__ int sMcount;

    const int tid = threadIdx.x;
    const int p   = blockIdx.x;
    const int py  = p/96, px = p - py*96;

    if (tid < 64) sfeat[tid] = g_feat[tid*HWLR + p];
    __syncthreads();

    // classifier & light hidden feature-dot (shared across 16 queries)
    if (tid < 64){
        float a = 0.0f;
#pragma unroll 8
        for (int c=0;c<64;c++) a += sfeat[c]*__ldg(&wc1[c*64+tid]);
        sCc[tid] = a;
    } else if (tid < 128){
        int t = tid - 64;
        float a = 0.0f;
#pragma unroll 8
        for (int c=0;c<64;c++) a += sfeat[c]*__ldg(&wl1[c*64+t]);
        sLl[t] = a;
    }
    __syncthreads();

    // per-query logits & light preds: warp w handles queries 2w, 2w+1
    {
        int wid = tid>>5, lane = tid&31;
#pragma unroll
        for (int mm=0;mm<2;mm++){
            int m = wid*2+mm;
            float l0=0,l1=0,q0=0,q1=0,q2=0;
#pragma unroll
            for (int hh=0;hh<2;hh++){
                int t = lane + hh*32;
                float hc = fmaxf(sCc[t] + g_offC[m*64+t], 0.0f);
                l0 += hc*__ldg(&wc2[t*2+0]);
                l1 += hc*__ldg(&wc2[t*2+1]);
                float hl = fmaxf(sLl[t] + g_offL[m*64+t], 0.0f);
                q0 += hl*__ldg(&wl2[t*3+0]);
                q1 += hl*__ldg(&wl2[t*3+1]);
                q2 += hl*__ldg(&wl2[t*3+2]);
            }
#pragma unroll
            for (int o=16;o>0;o>>=1){
                l0+=__shfl_xor_sync(0xffffffffu,l0,o);
                l1+=__shfl_xor_sync(0xffffffffu,l1,o);
                q0+=__shfl_xor_sync(0xffffffffu,q0,o);
                q1+=__shfl_xor_sync(0xffffffffu,q1,o);
                q2+=__shfl_xor_sync(0xffffffffu,q2,o);
            }
            if (lane==0){
                l0 += __ldg(&bc2[0]); l1 += __ldg(&bc2[1]);
                sFlag[m] = (l1 > l0) ? 1 : 0;   // argmax, tie -> 0 (matches jnp.argmax)
                sPredL[m][0] = q0 + __ldg(&bl2[0]);
                sPredL[m][1] = q1 + __ldg(&bl2[1]);
                sPredL[m][2] = q2 + __ldg(&bl2[2]);
            }
        }
    }
    __syncthreads();
    if (tid==0){
        int c=0;
        for (int m=0;m<16;m++){
            sInv[m] = -1;
            if (sFlag[m]){ sInv[m]=c; sMlist[c]=m; c++; }
        }
        sMcount = c;
    }
    __syncthreads();
    const int mcount = sMcount;

    // flag outputs
    if (tid < 16){
        int r = py*4 + (tid>>2), s = px*4 + (tid&3);
        int q = r*HHR + s;
        g_flag[q] = sFlag[tid];
        if (out_size >= 4*NQ) out[3*NQ + q] = (float)sFlag[tid];
    }

    if (mcount > 0){
        const int mpad = (mcount+3)&~3;
        // heavy layer1: shared feature-dot + per-query offset, compacted rows
        {
            float a = 0.0f;
#pragma unroll 8
            for (int c=0;c<64;c++) a += sfeat[c]*__ldg(&wh1[c*256+tid]);
            for (int i=0;i<mcount;i++){
                int m = sMlist[i];
                sA[i][tid] = fmaxf(a + g_offH[m*256+tid], 0.0f);
            }
            for (int i=mcount;i<mpad;i++) sA[i][tid] = 0.0f;
        }
        __syncthreads();
        switch (mpad){
            case 4:  heavy23<4 >(sA,sB,wh2,bh2,wh3,bh3,tid); break;
            case 8:  heavy23<8 >(sA,sB,wh2,bh2,wh3,bh3,tid); break;
            case 12: heavy23<12>(sA,sB,wh2,bh2,wh3,bh3,tid); break;
            default: heavy23<16>(sA,sB,wh2,bh2,wh3,bh3,tid); break;
        }
        // layer4: 256 -> 3 reductions on compacted rows (result of layer3 is in sA)
        {
            int wid = tid>>5, lane = tid&31;
            for (int i=wid; i<mcount; i+=8){
                float a0=0,a1=0,a2=0;
#pragma unroll
                for (int tt=0;tt<8;tt++){
                    int t = lane + tt*32;
                    float h = sA[i][t];
                    a0 += h*__ldg(&wh4[t*3+0]);
                    a1 += h*__ldg(&wh4[t*3+1]);
                    a2 += h*__ldg(&wh4[t*3+2]);
                }
#pragma unroll
                for (int o=16;o>0;o>>=1){
                    a0+=__shfl_xor_sync(0xffffffffu,a0,o);
                    a1+=__shfl_xor_sync(0xffffffffu,a1,o);
                    a2+=__shfl_xor_sync(0xffffffffu,a2,o);
                }
                if (lane==0){
                    sPredH[i][0] = a0 + __ldg(&bh4[0]);
                    sPredH[i][1] = a1 + __ldg(&bh4[1]);
                    sPredH[i][2] = a2 + __ldg(&bh4[2]);
                }
            }
        }
        __syncthreads();
    }

    // select branch, add bilinear residual, write pre-refinement pred
    if (tid < 48){
        int m = tid/3, j = tid - m*3;
        int r = py*4 + (m>>2), s = px*4 + (m&3);
        float v = sFlag[m] ? sPredH[sInv[m]][j] : sPredL[m][j];
        float cy = -1.0f + (2.0f*(float)r + 1.0f)/384.0f;
        float cx = -1.0f + (2.0f*(float)s + 1.0f)/384.0f;
        float fy = fminf(fmaxf((cy+1.0f)*96.0f/2.0f - 0.5f, 0.0f), 95.0f);
        float fx = fminf(fmaxf((cx+1.0f)*96.0f/2.0f - 0.5f, 0.0f), 95.0f);
        float y0f = floorf(fy), x0f = floorf(fx);
        float wy = fy - y0f, wx = fx - x0f;
        int y0 = (int)y0f, x0 = (int)x0f;
        int y1 = min(y0+1,95), x1 = min(x0+1,95);
        const float* img = lr + j*HWLR;
        float v00=__ldg(&img[y0*96+x0]), v01=__ldg(&img[y0*96+x1]);
        float v10=__ldg(&img[y1*96+x0]), v11=__ldg(&img[y1*96+x1]);
        v += v00*(1.0f-wy)*(1.0f-wx) + v01*(1.0f-wy)*wx
           + v10*wy*(1.0f-wx)       + v11*wy*wx;
        g_pred[j*NQ + r*HHR + s] = v;
    }
}

// ---------------- refinement: interior easy pixels adjacent to hard -> 3x3 mean ----------------
__global__ __launch_bounds__(256) void refine_kernel(float* __restrict__ out)
{
    int q = blockIdx.x*256 + threadIdx.x;
    if (q >= NQ) return;
    int r = q/HHR, s = q - r*HHR;
    float p0 = g_pred[q], p1 = g_pred[NQ+q], p2 = g_pred[2*NQ+q];
    if (r>0 && r<HHR-1 && s>0 && s<HHR-1 && g_flag[q]==0){
        int fs = 0;
#pragma unroll
        for (int dy=-1;dy<=1;dy++)
#pragma unroll
            for (int dx=-1;dx<=1;dx++)
                fs += g_flag[q + dy*HHR + dx];
        if (fs > 0){
            float s0=0,s1=0,s2=0;
#pragma unroll
            for (int dy=-1;dy<=1;dy++)
#pragma unroll
                for (int dx=-1;dx<=1;dx++){
                    int qq = q + dy*HHR + dx;
                    s0 += g_pred[qq];
                    s1 += g_pred[NQ+qq];
                    s2 += g_pred[2*NQ+qq];
                }
            p0 = s0/9.0f; p1 = s1/9.0f; p2 = s2/9.0f;
        }
    }
    out[q*3+0] = p0;
    out[q*3+1] = p1;
    out[q*3+2] = p2;
}

// ---------------- launch ----------------
extern "C" void kernel_launch(void* const* d_in, const int* in_sizes, int n_in,
                              void* d_out, int out_size)
{
    (void)in_sizes; (void)n_in;
    const float* lr  =(const float*)d_in[0];
    const float* cell=(const float*)d_in[2];
    const float* ew1 =(const float*)d_in[3];
    const float* eb1 =(const float*)d_in[4];
    const float* ew2 =(const float*)d_in[5];
    const float* eb2 =(const float*)d_in[6];
    const float* ew3 =(const float*)d_in[7];
    const float* eb3 =(const float*)d_in[8];
    const float* wh1 =(const float*)d_in[9];
    const float* bh1 =(const float*)d_in[10];
    const float* wh2 =(const float*)d_in[11];
    const float* bh2 =(const float*)d_in[12];
    const float* wh3 =(const float*)d_in[13];
    const float* bh3 =(const float*)d_in[14];
    const float* wh4 =(const float*)d_in[15];
    const float* bh4 =(const float*)d_in[16];
    const float* wl1 =(const float*)d_in[17];
    const float* bl1 =(const float*)d_in[18];
    const float* wl2 =(const float*)d_in[19];
    const float* bl2 =(const float*)d_in[20];
    const float* wc1 =(const float*)d_in[21];
    const float* bc1 =(const float*)d_in[22];
    const float* wc2 =(const float*)d_in[23];
    const float* bc2 =(const float*)d_in[24];
    float* out = (float*)d_out;

    float *b1, *b2, *feat;
    cudaGetSymbolAddress((void**)&b1,   g_b1);
    cudaGetSymbolAddress((void**)&b2,   g_b2);
    cudaGetSymbolAddress((void**)&feat, g_feat);

    precompute_kernel<<<1,256>>>(wh1,bh1,wc1,bc1,wl1,bl1,cell);
    conv3x3_kernel<3,true ><<<96,256>>>(lr, ew1, eb1, b1);
    conv3x3_kernel<64,true ><<<96,256>>>(b1, ew2, eb2, b2);
    conv3x3_kernel<64,false><<<96,256>>>(b2, ew3, eb3, feat);
    mlp_kernel<<<9216,256>>>(lr,
                             wh1,wh2,bh2,wh3,bh3,wh4,bh4,
                             wc1,wc2,bc2,
                             wl1,wl2,bl2,
                             out, out_size);
    refine_kernel<<<(NQ+255)/256,256>>>(out);
}

// round 6
// speedup vs baseline: 2.1374x; 2.1374x over previous
#include <cuda_runtime.h>
#include <cuda_bf16.h>
#include <math.h>
#include <stdint.h>

#define HLR   96
#define HWLR  9216
#define HHR   384
#define NQ    147456
#define NTILE 1152           // NQ/128 worst-case row tiles
#define KPAD  264            // A smem row pad (bf16 elems)
#define BPAD  40             // B smem row pad (bf16 elems)
#define FPAD  260            // h3 fp32 smem row pad
#define A_BYTES (128*KPAD*2)       // 67584 per component
#define B_COMP  (256*BPAD*2)       // 20480 per component
#define DSM_BYTES (2*A_BYTES + 2*B_COMP)   // 176128

// ---------------- static device scratch ----------------
__device__ float g_b1[64*HWLR];
__device__ float g_b2[64*HWLR];
__device__ float g_feat[64*HWLR];
__device__ float g_offH[16*256];
__device__ float g_offC[16*64];
__device__ float g_offL[16*64];
__device__ float g_pred[3*NQ];
__device__ int   g_flag[NQ];
__device__ int   g_cnt;
__device__ int   g_qidx[NQ];
__device__ float g_resid[3*NQ];
__device__ __align__(16) __nv_bfloat16 g_Ah[(size_t)NQ*256];
__device__ __align__(16) __nv_bfloat16 g_Al[(size_t)NQ*256];
__device__ __align__(16) __nv_bfloat16 g_W2h[65536], g_W2l[65536];
__device__ __align__(16) __nv_bfloat16 g_W3h[65536], g_W3l[65536];

// ---------------- helpers ----------------
__device__ __forceinline__ uint32_t smem_u32(const void* p){
    uint32_t a;
    asm("{ .reg .u64 t; cvta.to.shared.u64 t, %1; cvt.u32.u64 %0, t; }" : "=r"(a) : "l"(p));
    return a;
}
__device__ __forceinline__ void ldsm4(uint32_t r[4], uint32_t addr){
    asm volatile("ldmatrix.sync.aligned.m8n8.x4.shared.b16 {%0,%1,%2,%3}, [%4];"
        : "=r"(r[0]),"=r"(r[1]),"=r"(r[2]),"=r"(r[3]) : "r"(addr));
}
__device__ __forceinline__ void mma_bf16(float& c0, float& c1, float& c2, float& c3,
    const uint32_t a[4], uint32_t b0, uint32_t b1){
    asm volatile("mma.sync.aligned.m16n8k16.row.col.f32.bf16.bf16.f32 "
        "{%0,%1,%2,%3}, {%4,%5,%6,%7}, {%8,%9}, {%0,%1,%2,%3};"
        : "+f"(c0),"+f"(c1),"+f"(c2),"+f"(c3)
        : "r"(a[0]),"r"(a[1]),"r"(a[2]),"r"(a[3]),"r"(b0),"r"(b1));
}
__device__ __forceinline__ void split2(float v0, float v1, uint32_t& hi, uint32_t& lo){
    __nv_bfloat16 h0=__float2bfloat16(v0), h1=__float2bfloat16(v1);
    float f0=__bfloat162float(h0), f1=__bfloat162float(h1);
    __nv_bfloat16 l0=__float2bfloat16(v0-f0), l1=__float2bfloat16(v1-f1);
    hi = (uint32_t)__bfloat16_as_ushort(h0) | ((uint32_t)__bfloat16_as_ushort(h1)<<16);
    lo = (uint32_t)__bfloat16_as_ushort(l0) | ((uint32_t)__bfloat16_as_ushort(l1)<<16);
}

// ---------------- offset precompute + counter reset ----------------
__global__ void precompute_kernel(const float* __restrict__ wh1, const float* __restrict__ bh1,
                                  const float* __restrict__ wc1, const float* __restrict__ bc1,
                                  const float* __restrict__ wl1, const float* __restrict__ bl1,
                                  const float* __restrict__ cell)
{
    int t = threadIdx.x;
    if (t==0) g_cnt = 0;
    float rcy = cell[0]*96.0f, rcx = cell[1]*96.0f;
    float rel[4];
#pragma unroll
    for (int m=0;m<4;m++){
        float cy = -1.0f + (2.0f*(float)m + 1.0f)/384.0f;
        float fy = -1.0f + 1.0f/96.0f;
        rel[m] = (cy - fy)*96.0f;
    }
    for (int m=0;m<16;m++){
        float ry = rel[m>>2], rx = rel[m&3];
        g_offH[m*256+t] = ry*wh1[64*256+t] + rx*wh1[65*256+t]
                        + rcy*wh1[66*256+t] + rcx*wh1[67*256+t] + bh1[t];
        if (t < 64){
            g_offC[m*64+t] = ry*wc1[64*64+t] + rx*wc1[65*64+t]
                           + rcy*wc1[66*64+t] + rcx*wc1[67*64+t] + bc1[t];
            g_offL[m*64+t] = ry*wl1[64*64+t] + rx*wl1[65*64+t]
                           + rcy*wl1[66*64+t] + rcx*wl1[67*64+t] + bl1[t];
        }
    }
}

// ---------------- weight split to bf16 hi/lo, [n][k] images ----------------
__global__ void wsplit_kernel(const float* __restrict__ wh2, const float* __restrict__ wh3)
{
    int idx = blockIdx.x*256 + threadIdx.x;       // 0..131071
    int layer = idx >> 16;
    int e = idx & 65535;
    int k = e >> 8, n = e & 255;
    const float* w = layer ? wh3 : wh2;
    float v = w[k*256 + n];                        // W[n][k] image
    __nv_bfloat16 h = __float2bfloat16(v);
    float hf = __bfloat162float(h);
    __nv_bfloat16 l = __float2bfloat16(v - hf);
    uint32_t ei = (uint32_t)n*256u + (uint32_t)k;
    if (layer){ g_W3h[ei]=h; g_W3l[ei]=l; } else { g_W2h[ei]=h; g_W2l[ei]=l; }
}

// ---------------- 3x3 SAME conv; grid(96 rows, 4 oc-groups) ----------------
template<int IC, bool RELU>
__global__ __launch_bounds__(256) void conv3x3_kernel(
    const float* __restrict__ in, const float* __restrict__ w,
    const float* __restrict__ bias, float* __restrict__ out)
{
    constexpr int CH = (IC < 16) ? IC : 16;
    __shared__ float sIn[CH][3][100];
    __shared__ float sW[16][CH][9];
    const int y   = blockIdx.x;
    const int ocg = blockIdx.y;
    const int tid = threadIdx.x;
    const int ol  = tid >> 4;
    const int oc  = ocg*16 + ol;
    const int x0  = (tid & 15) * 6;
    float acc[6];
#pragma unroll
    for (int j=0;j<6;j++) acc[j]=0.0f;

    for (int c0=0;c0<IC;c0+=CH){
        __syncthreads();
        for (int idx=tid; idx<CH*3*96; idx+=256){
            int ic = idx/288, rem = idx - ic*288, ry = rem/96, x = rem - ry*96;
            int yy = y + ry - 1;
            float v = 0.0f;
            if (yy>=0 && yy<96) v = in[(c0+ic)*HWLR + yy*96 + x];
            sIn[ic][ry][x+1] = v;
        }
        for (int idx=tid; idx<CH*3; idx+=256){
            int ic = idx/3, ry = idx-ic*3;
            sIn[ic][ry][0]=0.0f; sIn[ic][ry][97]=0.0f;
        }
        for (int idx=tid; idx<16*CH*9; idx+=256){
            int o = idx/(CH*9), rem = idx - o*(CH*9), ic = rem/9, t = rem - ic*9;
            sW[o][ic][t] = w[((ocg*16+o)*IC + c0+ic)*9 + t];
        }
        __syncthreads();
#pragma unroll 2
        for (int ic=0; ic<CH; ic++){
            float r0[8],r1[8],r2[8];
#pragma unroll
            for (int d=0;d<8;d++){
                r0[d]=sIn[ic][0][x0+d]; r1[d]=sIn[ic][1][x0+d]; r2[d]=sIn[ic][2][x0+d];
            }
            float w00=sW[ol][ic][0], w01=sW[ol][ic][1], w02=sW[ol][ic][2];
            float w10=sW[ol][ic][3], w11=sW[ol][ic][4], w12=sW[ol][ic][5];
            float w20=sW[ol][ic][6], w21=sW[ol][ic][7], w22=sW[ol][ic][8];
#pragma unroll
            for (int j=0;j<6;j++){
                acc[j] += w00*r0[j]+w01*r0[j+1]+w02*r0[j+2]
                        + w10*r1[j]+w11*r1[j+1]+w12*r1[j+2]
                        + w20*r2[j]+w21*r2[j+1]+w22*r2[j+2];
            }
        }
    }
    float b = __ldg(bias+oc);
#pragma unroll
    for (int j=0;j<6;j++){
        float v = acc[j]+b;
        if (RELU) v = fmaxf(v,0.0f);
        out[oc*HWLR + y*96 + x0 + j] = v;
    }
}

// ---------------- kernel A: classifier + light + flags + residual + compacted h1 ----------------
__global__ __launch_bounds__(256) void mlpA_kernel(
    const float* __restrict__ lr,
    const float* __restrict__ wh1,
    const float* __restrict__ wc1, const float* __restrict__ wc2, const float* __restrict__ bc2,
    const float* __restrict__ wl1, const float* __restrict__ wl2, const float* __restrict__ bl2,
    float* __restrict__ out, int out_size)
{
    __shared__ float sfeat[64];
    __shared__ float sCc[64];
    __shared__ float sLl[64];
    __shared__ float sPredL[16][3];
    __shared__ int sFlag[16];
    __shared__ int sMlist[16];
    __shared__ int sInv[16];
    __shared__ int sMcount;
    __shared__ int sBase;

    const int tid = threadIdx.x;
    const int p   = blockIdx.x;
    const int py  = p/96, px = p - py*96;

    if (tid < 64) sfeat[tid] = g_feat[tid*HWLR + p];
    __syncthreads();

    if (tid < 64){
        float a = 0.0f;
#pragma unroll 8
        for (int c=0;c<64;c++) a += sfeat[c]*__ldg(&wc1[c*64+tid]);
        sCc[tid] = a;
    } else if (tid < 128){
        int t = tid - 64;
        float a = 0.0f;
#pragma unroll 8
        for (int c=0;c<64;c++) a += sfeat[c]*__ldg(&wl1[c*64+t]);
        sLl[t] = a;
    }
    __syncthreads();

    {
        int wid = tid>>5, lane = tid&31;
#pragma unroll
        for (int mm=0;mm<2;mm++){
            int m = wid*2+mm;
            float l0=0,l1=0,q0=0,q1=0,q2=0;
#pragma unroll
            for (int hh=0;hh<2;hh++){
                int t = lane + hh*32;
                float hc = fmaxf(sCc[t] + g_offC[m*64+t], 0.0f);
                l0 += hc*__ldg(&wc2[t*2+0]);
                l1 += hc*__ldg(&wc2[t*2+1]);
                float hl = fmaxf(sLl[t] + g_offL[m*64+t], 0.0f);
                q0 += hl*__ldg(&wl2[t*3+0]);
                q1 += hl*__ldg(&wl2[t*3+1]);
                q2 += hl*__ldg(&wl2[t*3+2]);
            }
#pragma unroll
            for (int o=16;o>0;o>>=1){
                l0+=__shfl_xor_sync(0xffffffffu,l0,o);
                l1+=__shfl_xor_sync(0xffffffffu,l1,o);
                q0+=__shfl_xor_sync(0xffffffffu,q0,o);
                q1+=__shfl_xor_sync(0xffffffffu,q1,o);
                q2+=__shfl_xor_sync(0xffffffffu,q2,o);
            }
            if (lane==0){
                l0 += __ldg(&bc2[0]); l1 += __ldg(&bc2[1]);
                sFlag[m] = (l1 > l0) ? 1 : 0;
                sPredL[m][0] = q0 + __ldg(&bl2[0]);
                sPredL[m][1] = q1 + __ldg(&bl2[1]);
                sPredL[m][2] = q2 + __ldg(&bl2[2]);
            }
        }
    }
    __syncthreads();
    if (tid==0){
        int c=0;
        for (int m=0;m<16;m++){
            sInv[m] = -1;
            if (sFlag[m]){ sInv[m]=c; sMlist[c]=m; c++; }
        }
        sMcount = c;
        sBase = (c>0) ? atomicAdd(&g_cnt, c) : 0;
    }
    __syncthreads();
    const int mcount = sMcount;
    const int base   = sBase;

    if (tid < 16){
        int r = py*4 + (tid>>2), s = px*4 + (tid&3);
        int q = r*HHR + s;
        g_flag[q] = sFlag[tid];
        if (out_size >= 4*NQ) out[3*NQ + q] = (float)sFlag[tid];
    }

    // heavy layer1 activations for hard queries, hi/lo split, [slot][256]
    if (mcount > 0){
        float a = 0.0f;
#pragma unroll 8
        for (int c=0;c<64;c++) a += sfeat[c]*__ldg(&wh1[c*256+tid]);
        for (int i=0;i<mcount;i++){
            int m = sMlist[i];
            int slot = base + i;
            float v = fmaxf(a + g_offH[m*256+tid], 0.0f);
            __nv_bfloat16 h = __float2bfloat16(v);
            float hf = __bfloat162float(h);
            __nv_bfloat16 l = __float2bfloat16(v - hf);
            g_Ah[(size_t)slot*256 + tid] = h;
            g_Al[(size_t)slot*256 + tid] = l;
        }
    }

    // residual + easy pred / hard bookkeeping
    if (tid < 48){
        int m = tid/3, j = tid - m*3;
        int r = py*4 + (m>>2), s = px*4 + (m&3);
        int q = r*HHR + s;
        float cy = -1.0f + (2.0f*(float)r + 1.0f)/384.0f;
        float cx = -1.0f + (2.0f*(float)s + 1.0f)/384.0f;
        float fy = fminf(fmaxf((cy+1.0f)*48.0f - 0.5f, 0.0f), 95.0f);
        float fx = fminf(fmaxf((cx+1.0f)*48.0f - 0.5f, 0.0f), 95.0f);
        float y0f = floorf(fy), x0f = floorf(fx);
        float wy = fy - y0f, wx = fx - x0f;
        int y0 = (int)y0f, x0 = (int)x0f;
        int y1 = min(y0+1,95), x1 = min(x0+1,95);
        const float* img = lr + j*HWLR;
        float v00=__ldg(&img[y0*96+x0]), v01=__ldg(&img[y0*96+x1]);
        float v10=__ldg(&img[y1*96+x0]), v11=__ldg(&img[y1*96+x1]);
        float resid = v00*(1.0f-wy)*(1.0f-wx) + v01*(1.0f-wy)*wx
                    + v10*wy*(1.0f-wx)       + v11*wy*wx;
        if (sFlag[m]==0){
            g_pred[j*NQ + q] = sPredL[m][j] + resid;
        } else {
            int slot = base + sInv[m];
            g_resid[slot*3 + j] = resid;
            if (j==0) g_qidx[slot] = q;
        }
    }
}

// ---------------- GEMM kernel: heavy layers 2,3,4 via mma.sync bf16 hi/lo ----------------
__global__ __launch_bounds__(256, 1) void gemm_kernel(
    const float* __restrict__ bh2, const float* __restrict__ bh3,
    const float* __restrict__ wh4, const float* __restrict__ bh4)
{
    extern __shared__ unsigned char sm[];
    __shared__ float sB2[256], sB3[256], sW4r[768], sBh4[4];
    __shared__ int s_cnt;

    const int tid = threadIdx.x, wid = tid>>5, lane = tid&31;
    if (tid==0) s_cnt = g_cnt;
    __syncthreads();
    const int cnt  = s_cnt;
    const int base = blockIdx.x*128;
    if (base >= cnt) return;
    const int valid = min(128, cnt - base);

    // biases / final weights
    sB2[tid]=__ldg(&bh2[tid]); sB3[tid]=__ldg(&bh3[tid]);
    sW4r[tid]=__ldg(&wh4[tid]); sW4r[256+tid]=__ldg(&wh4[256+tid]); sW4r[512+tid]=__ldg(&wh4[512+tid]);
    if (tid<3) sBh4[tid]=__ldg(&bh4[tid]);

    // copy A tile (hi+lo) into padded smem rows.
    // One 128x256 bf16 tile = 4096 uint4 = 128 rows x 32 uint4/row.
    {
        const uint4* srcH = (const uint4*)(g_Ah + (size_t)blockIdx.x*128*256);
        const uint4* srcL = (const uint4*)(g_Al + (size_t)blockIdx.x*128*256);
        for (int i=tid;i<4096;i+=256){
            int row = i>>5, c = i&31;                 // FIXED: 32 uint4 per 256-elem row
            *(uint4*)(sm + row*(KPAD*2) + c*16) = srcH[i];
            *(uint4*)(sm + A_BYTES + row*(KPAD*2) + c*16) = srcL[i];
        }
    }
    __syncthreads();

    const int wm = wid & 3;      // 0..3 row group (32 rows)
    const int wn = wid >> 2;     // 0..1 col group (64 cols per half)
    const uint32_t smA = smem_u32(sm);
    const uint32_t smB = smA + 2*A_BYTES;

    float acc[128];
#pragma unroll
    for (int i=0;i<128;i++) acc[i]=0.0f;

    for (int L=0; L<2; L++){
        const __nv_bfloat16* Wh = L ? g_W3h : g_W2h;
        const __nv_bfloat16* Wl = L ? g_W3l : g_W2l;
        for (int kc=0; kc<8; kc++){
            // stage B chunk: [256 n][32 k] hi+lo (per n: 4 uint4 = 32 bf16)
            for (int i=tid;i<2048;i+=256){
                int comp = i>>10, e = i&1023, n = e>>2, c4 = e&3;
                const uint4* src = (const uint4*)((comp ? Wl : Wh) + n*256 + kc*32);
                *(uint4*)(sm + 2*A_BYTES + comp*B_COMP + n*(BPAD*2) + c4*16) = src[c4];
            }
            __syncthreads();
#pragma unroll
            for (int kk=0; kk<32; kk+=16){
                uint32_t ah[2][4], al[2][4];
#pragma unroll
                for (int mt=0; mt<2; mt++){
                    int r = wm*32 + mt*16 + (lane&7) + ((lane>>3)&1)*8;
                    int kcol = kc*32 + kk + (lane>>4)*8;
                    uint32_t aAddr = smA + (uint32_t)(r*KPAD + kcol)*2u;
                    ldsm4(ah[mt], aAddr);
                    ldsm4(al[mt], aAddr + A_BYTES);
                }
#pragma unroll
                for (int half=0; half<2; half++){
#pragma unroll
                    for (int ntp=0; ntp<4; ntp++){
                        int n = half*128 + wn*64 + ntp*16 + (lane>>4)*8 + (lane&7);
                        int kl = kk + ((lane>>3)&1)*8;
                        uint32_t bAddr = smB + (uint32_t)(n*BPAD + kl)*2u;
                        uint32_t bh[4], bl[4];
                        ldsm4(bh, bAddr);
                        ldsm4(bl, bAddr + B_COMP);
#pragma unroll
                        for (int mt=0; mt<2; mt++){
#pragma unroll
                            for (int s2=0; s2<2; s2++){
                                const int ci = (((half*2+mt)*8) + (ntp*2+s2))*4;
                                mma_bf16(acc[ci],acc[ci+1],acc[ci+2],acc[ci+3], ah[mt], bh[s2*2], bh[s2*2+1]);
                                mma_bf16(acc[ci],acc[ci+1],acc[ci+2],acc[ci+3], al[mt], bh[s2*2], bh[s2*2+1]);
                                mma_bf16(acc[ci],acc[ci+1],acc[ci+2],acc[ci+3], ah[mt], bl[s2*2], bl[s2*2+1]);
                            }
                        }
                    }
                }
            }
            __syncthreads();
        }

        if (L==0){
            // epilogue: h2 = relu(D + bh2) -> hi/lo back into A smem
#pragma unroll
            for (int half=0; half<2; half++){
#pragma unroll
                for (int mt=0; mt<2; mt++){
#pragma unroll
                    for (int nt=0; nt<8; nt++){
                        const int ci = (((half*2+mt)*8) + nt)*4;
                        int rowA = wm*32 + mt*16 + (lane>>2);
                        int col0 = half*128 + wn*64 + nt*8 + (lane&3)*2;
                        uint32_t hi, lo;
                        split2(fmaxf(acc[ci+0]+sB2[col0],0.0f), fmaxf(acc[ci+1]+sB2[col0+1],0.0f), hi, lo);
                        *(uint32_t*)(sm + rowA*(KPAD*2) + col0*2) = hi;
                        *(uint32_t*)(sm + A_BYTES + rowA*(KPAD*2) + col0*2) = lo;
                        split2(fmaxf(acc[ci+2]+sB2[col0],0.0f), fmaxf(acc[ci+3]+sB2[col0+1],0.0f), hi, lo);
                        *(uint32_t*)(sm + (rowA+8)*(KPAD*2) + col0*2) = hi;
                        *(uint32_t*)(sm + A_BYTES + (rowA+8)*(KPAD*2) + col0*2) = lo;
                        acc[ci+0]=0.0f; acc[ci+1]=0.0f; acc[ci+2]=0.0f; acc[ci+3]=0.0f;
                    }
                }
            }
            __syncthreads();
        }
    }

    // final: h3 = relu(D + bh3) -> fp32 smem, then 256->3 reduction
    float* sF = (float*)sm;
#pragma unroll
    for (int half=0; half<2; half++){
#pragma unroll
        for (int mt=0; mt<2; mt++){
#pragma unroll
            for (int nt=0; nt<8; nt++){
                const int ci = (((half*2+mt)*8) + nt)*4;
                int rowA = wm*32 + mt*16 + (lane>>2);
                int col0 = half*128 + wn*64 + nt*8 + (lane&3)*2;
                sF[rowA*FPAD + col0]     = fmaxf(acc[ci+0]+sB3[col0],   0.0f);
                sF[rowA*FPAD + col0+1]   = fmaxf(acc[ci+1]+sB3[col0+1], 0.0f);
                sF[(rowA+8)*FPAD + col0]   = fmaxf(acc[ci+2]+sB3[col0],   0.0f);
                sF[(rowA+8)*FPAD + col0+1] = fmaxf(acc[ci+3]+sB3[col0+1], 0.0f);
            }
        }
    }
    __syncthreads();

    {
        int row = tid>>1, hf = tid&1;
        const float4* rp = (const float4*)(sF + row*FPAD + hf*128);
        float a0=0,a1=0,a2=0;
#pragma unroll 8
        for (int j=0;j<32;j++){
            float4 v = rp[j];
            int cb = hf*128 + j*4;
            a0 += v.x*sW4r[cb*3+0] + v.y*sW4r[(cb+1)*3+0] + v.z*sW4r[(cb+2)*3+0] + v.w*sW4r[(cb+3)*3+0];
            a1 += v.x*sW4r[cb*3+1] + v.y*sW4r[(cb+1)*3+1] + v.z*sW4r[(cb+2)*3+1] + v.w*sW4r[(cb+3)*3+1];
            a2 += v.x*sW4r[cb*3+2] + v.y*sW4r[(cb+1)*3+2] + v.z*sW4r[(cb+2)*3+2] + v.w*sW4r[(cb+3)*3+2];
        }
        a0 += __shfl_xor_sync(0xffffffffu, a0, 1);
        a1 += __shfl_xor_sync(0xffffffffu, a1, 1);
        a2 += __shfl_xor_sync(0xffffffffu, a2, 1);
        if (hf==0 && row < valid){
            int slot = base + row;
            int q = g_qidx[slot];
            g_pred[       q] = a0 + sBh4[0] + g_resid[slot*3+0];
            g_pred[  NQ + q] = a1 + sBh4[1] + g_resid[slot*3+1];
            g_pred[2*NQ + q] = a2 + sBh4[2] + g_resid[slot*3+2];
        }
    }
}

// ---------------- refinement ----------------
__global__ __launch_bounds__(256) void refine_kernel(float* __restrict__ out)
{
    int q = blockIdx.x*256 + threadIdx.x;
    if (q >= NQ) return;
    int r = q/HHR, s = q - r*HHR;
    float p0 = g_pred[q], p1 = g_pred[NQ+q], p2 = g_pred[2*NQ+q];
    if (r>0 && r<HHR-1 && s>0 && s<HHR-1 && g_flag[q]==0){
        int fs = 0;
#pragma unroll
        for (int dy=-1;dy<=1;dy++)
#pragma unroll
            for (int dx=-1;dx<=1;dx++)
                fs += g_flag[q + dy*HHR + dx];
        if (fs > 0){
            float s0=0,s1=0,s2=0;
#pragma unroll
            for (int dy=-1;dy<=1;dy++)
#pragma unroll
                for (int dx=-1;dx<=1;dx++){
                    int qq = q + dy*HHR + dx;
                    s0 += g_pred[qq];
                    s1 += g_pred[NQ+qq];
                    s2 += g_pred[2*NQ+qq];
                }
            p0 = s0/9.0f; p1 = s1/9.0f; p2 = s2/9.0f;
        }
    }
    out[q*3+0] = p0;
    out[q*3+1] = p1;
    out[q*3+2] = p2;
}

// ---------------- launch ----------------
extern "C" void kernel_launch(void* const* d_in, const int* in_sizes, int n_in,
                              void* d_out, int out_size)
{
    (void)in_sizes; (void)n_in;
    const float* lr  =(const float*)d_in[0];
    const float* cell=(const float*)d_in[2];
    const float* ew1 =(const float*)d_in[3];
    const float* eb1 =(const float*)d_in[4];
    const float* ew2 =(const float*)d_in[5];
    const float* eb2 =(const float*)d_in[6];
    const float* ew3 =(const float*)d_in[7];
    const float* eb3 =(const float*)d_in[8];
    const float* wh1 =(const float*)d_in[9];
    const float* bh1 =(const float*)d_in[10];
    const float* wh2 =(const float*)d_in[11];
    const float* bh2 =(const float*)d_in[12];
    const float* wh3 =(const float*)d_in[13];
    const float* bh3 =(const float*)d_in[14];
    const float* wh4 =(const float*)d_in[15];
    const float* bh4 =(const float*)d_in[16];
    const float* wl1 =(const float*)d_in[17];
    const float* bl1 =(const float*)d_in[18];
    const float* wl2 =(const float*)d_in[19];
    const float* bl2 =(const float*)d_in[20];
    const float* wc1 =(const float*)d_in[21];
    const float* bc1 =(const float*)d_in[22];
    const float* wc2 =(const float*)d_in[23];
    const float* bc2 =(const float*)d_in[24];
    float* out = (float*)d_out;

    float *b1, *b2, *feat;
    cudaGetSymbolAddress((void**)&b1,   g_b1);
    cudaGetSymbolAddress((void**)&b2,   g_b2);
    cudaGetSymbolAddress((void**)&feat, g_feat);

    cudaFuncSetAttribute(gemm_kernel, cudaFuncAttributeMaxDynamicSharedMemorySize, DSM_BYTES);

    precompute_kernel<<<1,256>>>(wh1,bh1,wc1,bc1,wl1,bl1,cell);
    wsplit_kernel<<<512,256>>>(wh2, wh3);
    conv3x3_kernel<3 ,true ><<<dim3(96,4),256>>>(lr, ew1, eb1, b1);
    conv3x3_kernel<64,true ><<<dim3(96,4),256>>>(b1, ew2, eb2, b2);
    conv3x3_kernel<64,false><<<dim3(96,4),256>>>(b2, ew3, eb3, feat);
    mlpA_kernel<<<9216,256>>>(lr, wh1, wc1, wc2, bc2, wl1, wl2, bl2, out, out_size);
    gemm_kernel<<<NTILE,256,DSM_BYTES>>>(bh2, bh3, wh4, bh4);
    refine_kernel<<<(NQ+255)/256,256>>>(out);
}

// round 7
// speedup vs baseline: 2.1931x; 1.0260x over previous
#include <cuda_runtime.h>
#include <cuda_bf16.h>
#include <math.h>
#include <stdint.h>

#define HLR   96
#define HWLR  9216
#define HHR   384
#define NQ    147456
#define NTILE 1152           // NQ/128 worst-case row tiles
#define KPAD  264            // A smem row pad (bf16 elems)
#define BPAD  40             // B smem row pad (bf16 elems)
#define FPAD  260            // h3 fp32 smem row pad
#define A_BYTES (128*KPAD*2)       // 67584 per component
#define B_COMP  (256*BPAD*2)       // 20480 per component
#define DSM_BYTES (2*A_BYTES + 4*B_COMP)   // 135168 + 81920 = 217088

// ---------------- static device scratch ----------------
__device__ float g_b1[64*HWLR];
__device__ float g_b2[64*HWLR];
__device__ float g_feat[64*HWLR];
__device__ float g_H[(size_t)HWLR*384];   // per-pixel layer-1 dots: [p][0:64)=wc1, [64:128)=wl1, [128:384)=wh1
__device__ float g_offH[16*256];
__device__ float g_offC[16*64];
__device__ float g_offL[16*64];
__device__ float g_pred[3*NQ];
__device__ int   g_flag[NQ];
__device__ int   g_cnt;
__device__ int   g_qidx[NQ];
__device__ float g_resid[3*NQ];
__device__ __align__(16) __nv_bfloat16 g_Ah[(size_t)NQ*256];
__device__ __align__(16) __nv_bfloat16 g_Al[(size_t)NQ*256];
__device__ __align__(16) __nv_bfloat16 g_W2h[65536], g_W2l[65536];
__device__ __align__(16) __nv_bfloat16 g_W3h[65536], g_W3l[65536];

// ---------------- helpers ----------------
__device__ __forceinline__ uint32_t smem_u32(const void* p){
    uint32_t a;
    asm("{ .reg .u64 t; cvta.to.shared.u64 t, %1; cvt.u32.u64 %0, t; }" : "=r"(a) : "l"(p));
    return a;
}
__device__ __forceinline__ void ldsm4(uint32_t r[4], uint32_t addr){
    asm volatile("ldmatrix.sync.aligned.m8n8.x4.shared.b16 {%0,%1,%2,%3}, [%4];"
        : "=r"(r[0]),"=r"(r[1]),"=r"(r[2]),"=r"(r[3]) : "r"(addr));
}
__device__ __forceinline__ void mma_bf16(float& c0, float& c1, float& c2, float& c3,
    const uint32_t a[4], uint32_t b0, uint32_t b1){
    asm volatile("mma.sync.aligned.m16n8k16.row.col.f32.bf16.bf16.f32 "
        "{%0,%1,%2,%3}, {%4,%5,%6,%7}, {%8,%9}, {%0,%1,%2,%3};"
        : "+f"(c0),"+f"(c1),"+f"(c2),"+f"(c3)
        : "r"(a[0]),"r"(a[1]),"r"(a[2]),"r"(a[3]),"r"(b0),"r"(b1));
}
__device__ __forceinline__ void split2(float v0, float v1, uint32_t& hi, uint32_t& lo){
    __nv_bfloat16 h0=__float2bfloat16(v0), h1=__float2bfloat16(v1);
    float f0=__bfloat162float(h0), f1=__bfloat162float(h1);
    __nv_bfloat16 l0=__float2bfloat16(v0-f0), l1=__float2bfloat16(v1-f1);
    hi = (uint32_t)__bfloat16_as_ushort(h0) | ((uint32_t)__bfloat16_as_ushort(h1)<<16);
    lo = (uint32_t)__bfloat16_as_ushort(l0) | ((uint32_t)__bfloat16_as_ushort(l1)<<16);
}
__device__ __forceinline__ void cp16(uint32_t dst, const void* src){
    asm volatile("cp.async.cg.shared.global [%0], [%1], 16;" :: "r"(dst), "l"(src));
}

// ---------------- offset precompute + counter reset ----------------
__global__ void precompute_kernel(const float* __restrict__ wh1, const float* __restrict__ bh1,
                                  const float* __restrict__ wc1, const float* __restrict__ bc1,
                                  const float* __restrict__ wl1, const float* __restrict__ bl1,
                                  const float* __restrict__ cell)
{
    int t = threadIdx.x;
    if (t==0) g_cnt = 0;
    float rcy = cell[0]*96.0f, rcx = cell[1]*96.0f;
    float rel[4];
#pragma unroll
    for (int m=0;m<4;m++){
        float cy = -1.0f + (2.0f*(float)m + 1.0f)/384.0f;
        float fy = -1.0f + 1.0f/96.0f;
        rel[m] = (cy - fy)*96.0f;
    }
    for (int m=0;m<16;m++){
        float ry = rel[m>>2], rx = rel[m&3];
        g_offH[m*256+t] = ry*wh1[64*256+t] + rx*wh1[65*256+t]
                        + rcy*wh1[66*256+t] + rcx*wh1[67*256+t] + bh1[t];
        if (t < 64){
            g_offC[m*64+t] = ry*wc1[64*64+t] + rx*wc1[65*64+t]
                           + rcy*wc1[66*64+t] + rcx*wc1[67*64+t] + bc1[t];
            g_offL[m*64+t] = ry*wl1[64*64+t] + rx*wl1[65*64+t]
                           + rcy*wl1[66*64+t] + rcx*wl1[67*64+t] + bl1[t];
        }
    }
}

// ---------------- weight split to bf16 hi/lo, [n][k] images ----------------
__global__ void wsplit_kernel(const float* __restrict__ wh2, const float* __restrict__ wh3)
{
    int idx = blockIdx.x*256 + threadIdx.x;       // 0..131071
    int layer = idx >> 16;
    int e = idx & 65535;
    int k = e >> 8, n = e & 255;
    const float* w = layer ? wh3 : wh2;
    float v = w[k*256 + n];                        // W[n][k] image
    __nv_bfloat16 h = __float2bfloat16(v);
    float hf = __bfloat162float(h);
    __nv_bfloat16 l = __float2bfloat16(v - hf);
    uint32_t ei = (uint32_t)n*256u + (uint32_t)k;
    if (layer){ g_W3h[ei]=h; g_W3l[ei]=l; } else { g_W2h[ei]=h; g_W2l[ei]=l; }
}

// ---------------- 3x3 SAME conv; grid(96 rows, 4 oc-groups); 128 thr, 2oc x 6px ----------------
template<int IC, bool RELU>
__global__ __launch_bounds__(128) void conv3x3_kernel(
    const float* __restrict__ in, const float* __restrict__ w,
    const float* __restrict__ bias, float* __restrict__ out)
{
    constexpr int CH = (IC < 16) ? IC : 16;
    __shared__ float sIn[CH][3][100];
    __shared__ float sW[16][CH][9];
    const int y   = blockIdx.x;
    const int ocg = blockIdx.y;
    const int tid = threadIdx.x;
    const int ol  = tid >> 4;                 // 0..7 -> oc pair
    const int oc0 = ocg*16 + ol*2;
    const int x0  = (tid & 15) * 6;
    float acc[2][6];
#pragma unroll
    for (int o=0;o<2;o++)
#pragma unroll
        for (int j=0;j<6;j++) acc[o][j]=0.0f;

    for (int c0=0;c0<IC;c0+=CH){
        __syncthreads();
        for (int idx=tid; idx<CH*3*96; idx+=128){
            int ic = idx/288, rem = idx - ic*288, ry = rem/96, x = rem - ry*96;
            int yy = y + ry - 1;
            float v = 0.0f;
            if (yy>=0 && yy<96) v = in[(c0+ic)*HWLR + yy*96 + x];
            sIn[ic][ry][x+1] = v;
        }
        for (int idx=tid; idx<CH*3; idx+=128){
            int ic = idx/3, ry = idx-ic*3;
            sIn[ic][ry][0]=0.0f; sIn[ic][ry][97]=0.0f;
        }
        for (int idx=tid; idx<16*CH*9; idx+=128){
            int o = idx/(CH*9), rem = idx - o*(CH*9), ic = rem/9, t = rem - ic*9;
            sW[o][ic][t] = w[((ocg*16+o)*IC + c0+ic)*9 + t];
        }
        __syncthreads();
#pragma unroll 2
        for (int ic=0; ic<CH; ic++){
            float r0[8],r1[8],r2[8];
#pragma unroll
            for (int d=0;d<8;d++){
                r0[d]=sIn[ic][0][x0+d]; r1[d]=sIn[ic][1][x0+d]; r2[d]=sIn[ic][2][x0+d];
            }
#pragma unroll
            for (int o=0;o<2;o++){
                float w00=sW[ol*2+o][ic][0], w01=sW[ol*2+o][ic][1], w02=sW[ol*2+o][ic][2];
                float w10=sW[ol*2+o][ic][3], w11=sW[ol*2+o][ic][4], w12=sW[ol*2+o][ic][5];
                float w20=sW[ol*2+o][ic][6], w21=sW[ol*2+o][ic][7], w22=sW[ol*2+o][ic][8];
#pragma unroll
                for (int j=0;j<6;j++){
                    acc[o][j] += w00*r0[j]+w01*r0[j+1]+w02*r0[j+2]
                               + w10*r1[j]+w11*r1[j+1]+w12*r1[j+2]
                               + w20*r2[j]+w21*r2[j+1]+w22*r2[j+2];
                }
            }
        }
    }
#pragma unroll
    for (int o=0;o<2;o++){
        float b = __ldg(bias+oc0+o);
#pragma unroll
        for (int j=0;j<6;j++){
            float v = acc[o][j]+b;
            if (RELU) v = fmaxf(v,0.0f);
            out[(oc0+o)*HWLR + y*96 + x0 + j] = v;
        }
    }
}

// ---------------- front GEMM: g_H[p][384] = feat[p][64] x [wc1|wl1|wh1] ----------------
// grid 384 (24 px/block), block 256: thread = 6px x 6cols.
__global__ __launch_bounds__(256) void front_kernel(
    const float* __restrict__ wc1, const float* __restrict__ wl1, const float* __restrict__ wh1)
{
    __shared__ float sF[64][25];
    __shared__ float sW[16][385];
    const int tid = threadIdx.x;
    const int P0  = blockIdx.x*24;
    const int txp = tid & 3;        // 4 px-groups x 6
    const int txc = tid >> 2;       // 64 col-groups x 6

    for (int i=tid; i<64*24; i+=256){
        int c = i/24, pl = i - c*24;
        sF[c][pl] = g_feat[c*HWLR + P0 + pl];
    }

    float acc[6][6];
#pragma unroll
    for (int i=0;i<6;i++)
#pragma unroll
        for (int j=0;j<6;j++) acc[i][j]=0.0f;

    for (int c0=0; c0<64; c0+=16){
        __syncthreads();
        for (int i=tid; i<16*384; i+=256){
            int cc = i/384, n = i - cc*384;
            int c = c0 + cc;
            float w;
            if (n < 64)        w = wc1[c*64 + n];
            else if (n < 128)  w = wl1[c*64 + (n-64)];
            else               w = wh1[c*256 + (n-128)];
            sW[cc][n] = w;
        }
        __syncthreads();
#pragma unroll
        for (int cc=0; cc<16; cc++){
            float f[6], w[6];
#pragma unroll
            for (int j=0;j<6;j++) f[j] = sF[c0+cc][txp*6+j];
#pragma unroll
            for (int i=0;i<6;i++) w[i] = sW[cc][txc*6+i];
#pragma unroll
            for (int i=0;i<6;i++)
#pragma unroll
                for (int j=0;j<6;j++) acc[i][j] += w[i]*f[j];
        }
    }
#pragma unroll
    for (int j=0;j<6;j++)
#pragma unroll
        for (int i=0;i<6;i++)
            g_H[(size_t)(P0 + txp*6 + j)*384 + txc*6 + i] = acc[i][j];
}

// ---------------- mlpB: per-pixel classify/light/compact; 4 px per block ----------------
__global__ __launch_bounds__(256) void mlpB_kernel(
    const float* __restrict__ lr,
    const float* __restrict__ wc2, const float* __restrict__ bc2,
    const float* __restrict__ wl2, const float* __restrict__ bl2,
    float* __restrict__ out, int out_size)
{
    __shared__ float sHc[4][64];
    __shared__ float sHl[4][64];
    __shared__ float sHh[4][256];
    __shared__ float sPredL[4][16][3];
    __shared__ int sFlag[4][16];
    __shared__ int sMlist[4][16];
    __shared__ int sInv[4][16];
    __shared__ int sMcount[4];
    __shared__ int sBase[4];

    const int tid = threadIdx.x;
    const int p0  = blockIdx.x*4;

    // load dots
#pragma unroll
    for (int pp=0;pp<4;pp++) sHh[pp][tid] = g_H[(size_t)(p0+pp)*384 + 128 + tid];
    {
        int pp = tid>>6, c = tid&63;
        sHc[pp][c] = g_H[(size_t)(p0+pp)*384 + c];
        sHl[pp][c] = g_H[(size_t)(p0+pp)*384 + 64 + c];
    }
    __syncthreads();

    // logits & light preds: warp w handles 8 queries (64 = 4px x 16)
    {
        int wid = tid>>5, lane = tid&31;
#pragma unroll
        for (int i=0;i<8;i++){
            int qq = wid*8 + i;
            int pp = qq>>4, m = qq&15;
            float l0=0,l1=0,q0=0,q1=0,q2=0;
#pragma unroll
            for (int hh=0;hh<2;hh++){
                int t = lane + hh*32;
                float hc = fmaxf(sHc[pp][t] + g_offC[m*64+t], 0.0f);
                l0 += hc*__ldg(&wc2[t*2+0]);
                l1 += hc*__ldg(&wc2[t*2+1]);
                float hl = fmaxf(sHl[pp][t] + g_offL[m*64+t], 0.0f);
                q0 += hl*__ldg(&wl2[t*3+0]);
                q1 += hl*__ldg(&wl2[t*3+1]);
                q2 += hl*__ldg(&wl2[t*3+2]);
            }
#pragma unroll
            for (int o=16;o>0;o>>=1){
                l0+=__shfl_xor_sync(0xffffffffu,l0,o);
                l1+=__shfl_xor_sync(0xffffffffu,l1,o);
                q0+=__shfl_xor_sync(0xffffffffu,q0,o);
                q1+=__shfl_xor_sync(0xffffffffu,q1,o);
                q2+=__shfl_xor_sync(0xffffffffu,q2,o);
            }
            if (lane==0){
                l0 += __ldg(&bc2[0]); l1 += __ldg(&bc2[1]);
                sFlag[pp][m] = (l1 > l0) ? 1 : 0;
                sPredL[pp][m][0] = q0 + __ldg(&bl2[0]);
                sPredL[pp][m][1] = q1 + __ldg(&bl2[1]);
                sPredL[pp][m][2] = q2 + __ldg(&bl2[2]);
            }
        }
    }
    __syncthreads();

    // compaction (4 threads, one per pixel)
    if (tid < 4){
        int c=0;
        for (int m=0;m<16;m++){
            sInv[tid][m] = -1;
            if (sFlag[tid][m]){ sInv[tid][m]=c; sMlist[tid][c]=m; c++; }
        }
        sMcount[tid] = c;
        sBase[tid] = (c>0) ? atomicAdd(&g_cnt, c) : 0;
    }
    __syncthreads();

    // flag outputs
    if (tid < 64){
        int pp = tid>>4, mm = tid&15;
        int p = p0+pp, py = p/96, px = p - py*96;
        int r = py*4 + (mm>>2), s = px*4 + (mm&3);
        int q = r*HHR + s;
        g_flag[q] = sFlag[pp][mm];
        if (out_size >= 4*NQ) out[3*NQ + q] = (float)sFlag[pp][mm];
    }

    // heavy-h1 split for hard queries
#pragma unroll
    for (int pp=0;pp<4;pp++){
        int mc = sMcount[pp];
        if (mc == 0) continue;
        float hv = sHh[pp][tid];
        int bb = sBase[pp];
        for (int i=0;i<mc;i++){
            int m = sMlist[pp][i];
            float v = fmaxf(hv + g_offH[m*256+tid], 0.0f);
            __nv_bfloat16 h = __float2bfloat16(v);
            float hf = __bfloat162float(h);
            __nv_bfloat16 l = __float2bfloat16(v - hf);
            g_Ah[(size_t)(bb+i)*256 + tid] = h;
            g_Al[(size_t)(bb+i)*256 + tid] = l;
        }
    }

    // residual + easy pred / hard bookkeeping (4px x 16q x 3ch = 192)
    if (tid < 192){
        int pp = tid/48, r3 = tid - pp*48;
        int m = r3/3, j = r3 - m*3;
        int p = p0+pp, py = p/96, px = p - py*96;
        int r = py*4 + (m>>2), s = px*4 + (m&3);
        int q = r*HHR + s;
        float cy = -1.0f + (2.0f*(float)r + 1.0f)/384.0f;
        float cx = -1.0f + (2.0f*(float)s + 1.0f)/384.0f;
        float fy = fminf(fmaxf((cy+1.0f)*48.0f - 0.5f, 0.0f), 95.0f);
        float fx = fminf(fmaxf((cx+1.0f)*48.0f - 0.5f, 0.0f), 95.0f);
        float y0f = floorf(fy), x0f = floorf(fx);
        float wy = fy - y0f, wx = fx - x0f;
        int y0 = (int)y0f, x0 = (int)x0f;
        int y1 = min(y0+1,95), x1 = min(x0+1,95);
        const float* img = lr + j*HWLR;
        float v00=__ldg(&img[y0*96+x0]), v01=__ldg(&img[y0*96+x1]);
        float v10=__ldg(&img[y1*96+x0]), v11=__ldg(&img[y1*96+x1]);
        float resid = v00*(1.0f-wy)*(1.0f-wx) + v01*(1.0f-wy)*wx
                    + v10*wy*(1.0f-wx)       + v11*wy*wx;
        if (sFlag[pp][m]==0){
            g_pred[j*NQ + q] = sPredL[pp][m][j] + resid;
        } else {
            int slot = sBase[pp] + sInv[pp][m];
            g_resid[slot*3 + j] = resid;
            if (j==0) g_qidx[slot] = q;
        }
    }
}

// ---------------- B chunk stage via cp.async ----------------
__device__ __forceinline__ void stage_B(int tid, uint32_t bbase,
    const __nv_bfloat16* __restrict__ Wh, const __nv_bfloat16* __restrict__ Wl, int kc)
{
    for (int i=tid;i<2048;i+=256){
        int comp=i>>10, e=i&1023, n=e>>2, c4=e&3;
        const __nv_bfloat16* src = (comp?Wl:Wh) + n*256 + kc*32 + c4*8;
        cp16(bbase + (uint32_t)comp*B_COMP + (uint32_t)n*(BPAD*2) + (uint32_t)c4*16, src);
    }
    asm volatile("cp.async.commit_group;");
}

// ---------------- GEMM kernel: heavy layers 2,3,4 via mma.sync bf16 hi/lo ----------------
__global__ __launch_bounds__(256, 1) void gemm_kernel(
    const float* __restrict__ bh2, const float* __restrict__ bh3,
    const float* __restrict__ wh4, const float* __restrict__ bh4)
{
    extern __shared__ unsigned char sm[];
    __shared__ float sB2[256], sB3[256], sW4r[768], sBh4[4];
    __shared__ int s_cnt;

    const int tid = threadIdx.x, wid = tid>>5, lane = tid&31;
    if (tid==0) s_cnt = g_cnt;
    __syncthreads();
    const int cnt  = s_cnt;
    const int base = blockIdx.x*128;
    if (base >= cnt) return;
    const int valid = min(128, cnt - base);

    sB2[tid]=__ldg(&bh2[tid]); sB3[tid]=__ldg(&bh3[tid]);
    sW4r[tid]=__ldg(&wh4[tid]); sW4r[256+tid]=__ldg(&wh4[256+tid]); sW4r[512+tid]=__ldg(&wh4[512+tid]);
    if (tid<3) sBh4[tid]=__ldg(&bh4[tid]);

    // A tile (hi+lo): 4096 uint4 = 128 rows x 32 uint4
    {
        const uint4* srcH = (const uint4*)(g_Ah + (size_t)blockIdx.x*128*256);
        const uint4* srcL = (const uint4*)(g_Al + (size_t)blockIdx.x*128*256);
        for (int i=tid;i<4096;i+=256){
            int row = i>>5, c = i&31;
            *(uint4*)(sm + row*(KPAD*2) + c*16) = srcH[i];
            *(uint4*)(sm + A_BYTES + row*(KPAD*2) + c*16) = srcL[i];
        }
    }

    const int wm = wid & 3;
    const int wn = wid >> 2;
    const uint32_t smA = smem_u32(sm);
    const uint32_t smB = smA + 2*A_BYTES;

    float acc[128];
#pragma unroll
    for (int i=0;i<128;i++) acc[i]=0.0f;

    stage_B(tid, smB, g_W2h, g_W2l, 0);

    for (int idx=0; idx<16; idx++){
        if (idx < 15){
            int nx = idx+1;
            stage_B(tid, smB + (uint32_t)(nx&1)*(2*B_COMP),
                    (nx&8)?g_W3h:g_W2h, (nx&8)?g_W3l:g_W2l, nx&7);
            asm volatile("cp.async.wait_group 1;");
        } else {
            asm volatile("cp.async.wait_group 0;");
        }
        __syncthreads();

        const int kc = idx & 7;
        const uint32_t bB = smB + (uint32_t)(idx&1)*(2*B_COMP);
#pragma unroll
        for (int kk=0; kk<32; kk+=16){
            uint32_t ah[2][4], al[2][4];
#pragma unroll
            for (int mt=0; mt<2; mt++){
                int r = wm*32 + mt*16 + (lane&7) + ((lane>>3)&1)*8;
                int kcol = kc*32 + kk + (lane>>4)*8;
                uint32_t aAddr = smA + (uint32_t)(r*KPAD + kcol)*2u;
                ldsm4(ah[mt], aAddr);
                ldsm4(al[mt], aAddr + A_BYTES);
            }
#pragma unroll
            for (int half=0; half<2; half++){
#pragma unroll
                for (int ntp=0; ntp<4; ntp++){
                    int n = half*128 + wn*64 + ntp*16 + (lane>>4)*8 + (lane&7);
                    int kl = kk + ((lane>>3)&1)*8;
                    uint32_t bAddr = bB + (uint32_t)(n*BPAD + kl)*2u;
                    uint32_t bh[4], bl[4];
                    ldsm4(bh, bAddr);
                    ldsm4(bl, bAddr + B_COMP);
#pragma unroll
                    for (int mt=0; mt<2; mt++){
#pragma unroll
                        for (int s2=0; s2<2; s2++){
                            const int ci = (((half*2+mt)*8) + (ntp*2+s2))*4;
                            mma_bf16(acc[ci],acc[ci+1],acc[ci+2],acc[ci+3], ah[mt], bh[s2*2], bh[s2*2+1]);
                            mma_bf16(acc[ci],acc[ci+1],acc[ci+2],acc[ci+3], al[mt], bh[s2*2], bh[s2*2+1]);
                            mma_bf16(acc[ci],acc[ci+1],acc[ci+2],acc[ci+3], ah[mt], bl[s2*2], bl[s2*2+1]);
                        }
                    }
                }
            }
        }
        __syncthreads();

        if (idx == 7){
            // epilogue L2: h2 = relu(D + bh2) -> hi/lo back into A smem
#pragma unroll
            for (int half=0; half<2; half++){
#pragma unroll
                for (int mt=0; mt<2; mt++){
#pragma unroll
                    for (int nt=0; nt<8; nt++){
                        const int ci = (((half*2+mt)*8) + nt)*4;
                        int rowA = wm*32 + mt*16 + (lane>>2);
                        int col0 = half*128 + wn*64 + nt*8 + (lane&3)*2;
                        uint32_t hi, lo;
                        split2(fmaxf(acc[ci+0]+sB2[col0],0.0f), fmaxf(acc[ci+1]+sB2[col0+1],0.0f), hi, lo);
                        *(uint32_t*)(sm + rowA*(KPAD*2) + col0*2) = hi;
                        *(uint32_t*)(sm + A_BYTES + rowA*(KPAD*2) + col0*2) = lo;
                        split2(fmaxf(acc[ci+2]+sB2[col0],0.0f), fmaxf(acc[ci+3]+sB2[col0+1],0.0f), hi, lo);
                        *(uint32_t*)(sm + (rowA+8)*(KPAD*2) + col0*2) = hi;
                        *(uint32_t*)(sm + A_BYTES + (rowA+8)*(KPAD*2) + col0*2) = lo;
                        acc[ci+0]=0.0f; acc[ci+1]=0.0f; acc[ci+2]=0.0f; acc[ci+3]=0.0f;
                    }
                }
            }
            __syncthreads();
        }
    }

    // final: h3 = relu(D + bh3) -> fp32 smem (overwrites A region), then 256->3 reduction
    float* sF = (float*)sm;
#pragma unroll
    for (int half=0; half<2; half++){
#pragma unroll
        for (int mt=0; mt<2; mt++){
#pragma unroll
            for (int nt=0; nt<8; nt++){
                const int ci = (((half*2+mt)*8) + nt)*4;
                int rowA = wm*32 + mt*16 + (lane>>2);
                int col0 = half*128 + wn*64 + nt*8 + (lane&3)*2;
                sF[rowA*FPAD + col0]       = fmaxf(acc[ci+0]+sB3[col0],   0.0f);
                sF[rowA*FPAD + col0+1]     = fmaxf(acc[ci+1]+sB3[col0+1], 0.0f);
                sF[(rowA+8)*FPAD + col0]   = fmaxf(acc[ci+2]+sB3[col0],   0.0f);
                sF[(rowA+8)*FPAD + col0+1] = fmaxf(acc[ci+3]+sB3[col0+1], 0.0f);
            }
        }
    }
    __syncthreads();

    {
        int row = tid>>1, hf = tid&1;
        const float4* rp = (const float4*)(sF + row*FPAD + hf*128);
        float a0=0,a1=0,a2=0;
#pragma unroll 8
        for (int j=0;j<32;j++){
            float4 v = rp[j];
            int cb = hf*128 + j*4;
            a0 += v.x*sW4r[cb*3+0] + v.y*sW4r[(cb+1)*3+0] + v.z*sW4r[(cb+2)*3+0] + v.w*sW4r[(cb+3)*3+0];
            a1 += v.x*sW4r[cb*3+1] + v.y*sW4r[(cb+1)*3+1] + v.z*sW4r[(cb+2)*3+1] + v.w*sW4r[(cb+3)*3+1];
            a2 += v.x*sW4r[cb*3+2] + v.y*sW4r[(cb+1)*3+2] + v.z*sW4r[(cb+2)*3+2] + v.w*sW4r[(cb+3)*3+2];
        }
        a0 += __shfl_xor_sync(0xffffffffu, a0, 1);
        a1 += __shfl_xor_sync(0xffffffffu, a1, 1);
        a2 += __shfl_xor_sync(0xffffffffu, a2, 1);
        if (hf==0 && row < valid){
            int slot = base + row;
            int q = g_qidx[slot];
            g_pred[       q] = a0 + sBh4[0] + g_resid[slot*3+0];
            g_pred[  NQ + q] = a1 + sBh4[1] + g_resid[slot*3+1];
            g_pred[2*NQ + q] = a2 + sBh4[2] + g_resid[slot*3+2];
        }
    }
}

// ---------------- refinement ----------------
__global__ __launch_bounds__(256) void refine_kernel(float* __restrict__ out)
{
    int q = blockIdx.x*256 + threadIdx.x;
    if (q >= NQ) return;
    int r = q/HHR, s = q - r*HHR;
    float p0 = g_pred[q], p1 = g_pred[NQ+q], p2 = g_pred[2*NQ+q];
    if (r>0 && r<HHR-1 && s>0 && s<HHR-1 && g_flag[q]==0){
        int fs = 0;
#pragma unroll
        for (int dy=-1;dy<=1;dy++)
#pragma unroll
            for (int dx=-1;dx<=1;dx++)
                fs += g_flag[q + dy*HHR + dx];
        if (fs > 0){
            float s0=0,s1=0,s2=0;
#pragma unroll
            for (int dy=-1;dy<=1;dy++)
#pragma unroll
                for (int dx=-1;dx<=1;dx++){
                    int qq = q + dy*HHR + dx;
                    s0 += g_pred[qq];
                    s1 += g_pred[NQ+qq];
                    s2 += g_pred[2*NQ+qq];
                }
            p0 = s0/9.0f; p1 = s1/9.0f; p2 = s2/9.0f;
        }
    }
    out[q*3+0] = p0;
    out[q*3+1] = p1;
    out[q*3+2] = p2;
}

// ---------------- launch ----------------
extern "C" void kernel_launch(void* const* d_in, const int* in_sizes, int n_in,
                              void* d_out, int out_size)
{
    (void)in_sizes; (void)n_in;
    const float* lr  =(const float*)d_in[0];
    const float* cell=(const float*)d_in[2];
    const float* ew1 =(const float*)d_in[3];
    const float* eb1 =(const float*)d_in[4];
    const float* ew2 =(const float*)d_in[5];
    const float* eb2 =(const float*)d_in[6];
    const float* ew3 =(const float*)d_in[7];
    const float* eb3 =(const float*)d_in[8];
    const float* wh1 =(const float*)d_in[9];
    const float* bh1 =(const float*)d_in[10];
    const float* wh2 =(const float*)d_in[11];
    const float* bh2 =(const float*)d_in[12];
    const float* wh3 =(const float*)d_in[13];
    const float* bh3 =(const float*)d_in[14];
    const float* wh4 =(const float*)d_in[15];
    const float* bh4 =(const float*)d_in[16];
    const float* wl1 =(const float*)d_in[17];
    const float* bl1 =(const float*)d_in[18];
    const float* wl2 =(const float*)d_in[19];
    const float* bl2 =(const float*)d_in[20];
    const float* wc1 =(const float*)d_in[21];
    const float* bc1 =(const float*)d_in[22];
    const float* wc2 =(const float*)d_in[23];
    const float* bc2 =(const float*)d_in[24];
    float* out = (float*)d_out;

    float *b1, *b2, *feat;
    cudaGetSymbolAddress((void**)&b1,   g_b1);
    cudaGetSymbolAddress((void**)&b2,   g_b2);
    cudaGetSymbolAddress((void**)&feat, g_feat);

    cudaFuncSetAttribute(gemm_kernel, cudaFuncAttributeMaxDynamicSharedMemorySize, DSM_BYTES);

    precompute_kernel<<<1,256>>>(wh1,bh1,wc1,bc1,wl1,bl1,cell);
    wsplit_kernel<<<512,256>>>(wh2, wh3);
    conv3x3_kernel<3 ,true ><<<dim3(96,4),128>>>(lr, ew1, eb1, b1);
    conv3x3_kernel<64,true ><<<dim3(96,4),128>>>(b1, ew2, eb2, b2);
    conv3x3_kernel<64,false><<<dim3(96,4),128>>>(b2, ew3, eb3, feat);
    front_kernel<<<384,256>>>(wc1, wl1, wh1);
    mlpB_kernel<<<2304,256>>>(lr, wc2, bc2, wl2, bl2, out, out_size);
    gemm_kernel<<<NTILE,256,DSM_BYTES>>>(bh2, bh3, wh4, bh4);
    refine_kernel<<<(NQ+255)/256,256>>>(out);
}

// round 8
// speedup vs baseline: 2.8011x; 1.2772x over previous
#include <cuda_runtime.h>
#include <cuda_fp16.h>
#include <math.h>
#include <stdint.h>

#define HLR   96
#define HWLR  9216
#define HHR   384
#define NQ    147456
#define TR    64                   // GEMM tile rows
#define NT2   (NQ/TR)              // 2304 tiles
#define KPAD  264                  // A smem row pad (fp16 elems)
#define BPAD  40                   // B smem row pad (fp16 elems)
#define FPAD  260                  // h3 fp32 smem row pad
#define A_B   (TR*KPAD*2)          // 33792 bytes per A component
#define B_COMP (256*BPAD*2)        // 20480 bytes per B stage
#define DSM2  (2*A_B + 2*B_COMP)   // 108544

// ---------------- static device scratch ----------------
__device__ float g_b1[64*HWLR];
__device__ float g_b2[64*HWLR];
__device__ float g_feat[64*HWLR];
__device__ float g_H[(size_t)HWLR*384];   // [p][0:64)=wc1 dots, [64:128)=wl1, [128:384)=wh1
__device__ float g_offH[16*256];
__device__ float g_offC[16*64];
__device__ float g_offL[16*64];
__device__ float g_pred[3*NQ];
__device__ int   g_flag[NQ];
__device__ int   g_cnt;
__device__ int   g_qidx[NQ];
__device__ float g_resid[3*NQ];
__device__ __align__(16) __half g_W2h[65536];   // [n][k] fp16
__device__ __align__(16) __half g_W3h[65536];

// ---------------- helpers ----------------
__device__ __forceinline__ uint32_t smem_u32(const void* p){
    uint32_t a;
    asm("{ .reg .u64 t; cvta.to.shared.u64 t, %1; cvt.u32.u64 %0, t; }" : "=r"(a) : "l"(p));
    return a;
}
__device__ __forceinline__ void ldsm4(uint32_t r[4], uint32_t addr){
    asm volatile("ldmatrix.sync.aligned.m8n8.x4.shared.b16 {%0,%1,%2,%3}, [%4];"
        : "=r"(r[0]),"=r"(r[1]),"=r"(r[2]),"=r"(r[3]) : "r"(addr));
}
__device__ __forceinline__ void mma_f16(float& c0, float& c1, float& c2, float& c3,
    const uint32_t a[4], uint32_t b0, uint32_t b1){
    asm volatile("mma.sync.aligned.m16n8k16.row.col.f32.f16.f16.f32 "
        "{%0,%1,%2,%3}, {%4,%5,%6,%7}, {%8,%9}, {%0,%1,%2,%3};"
        : "+f"(c0),"+f"(c1),"+f"(c2),"+f"(c3)
        : "r"(a[0]),"r"(a[1]),"r"(a[2]),"r"(a[3]),"r"(b0),"r"(b1));
}
__device__ __forceinline__ void split2h(float v0, float v1, uint32_t& hi, uint32_t& lo){
    __half h0=__float2half(v0), h1=__float2half(v1);
    float f0=__half2float(h0), f1=__half2float(h1);
    __half l0=__float2half(v0-f0), l1=__float2half(v1-f1);
    hi = (uint32_t)__half_as_ushort(h0) | ((uint32_t)__half_as_ushort(h1)<<16);
    lo = (uint32_t)__half_as_ushort(l0) | ((uint32_t)__half_as_ushort(l1)<<16);
}
__device__ __forceinline__ void cp16(uint32_t dst, const void* src){
    asm volatile("cp.async.cg.shared.global [%0], [%1], 16;" :: "r"(dst), "l"(src));
}

// ---------------- offset precompute + counter reset ----------------
__global__ void precompute_kernel(const float* __restrict__ wh1, const float* __restrict__ bh1,
                                  const float* __restrict__ wc1, const float* __restrict__ bc1,
                                  const float* __restrict__ wl1, const float* __restrict__ bl1,
                                  const float* __restrict__ cell)
{
    int t = threadIdx.x;
    if (t==0) g_cnt = 0;
    float rcy = cell[0]*96.0f, rcx = cell[1]*96.0f;
    float rel[4];
#pragma unroll
    for (int m=0;m<4;m++){
        float cy = -1.0f + (2.0f*(float)m + 1.0f)/384.0f;
        float fy = -1.0f + 1.0f/96.0f;
        rel[m] = (cy - fy)*96.0f;
    }
    for (int m=0;m<16;m++){
        float ry = rel[m>>2], rx = rel[m&3];
        g_offH[m*256+t] = ry*wh1[64*256+t] + rx*wh1[65*256+t]
                        + rcy*wh1[66*256+t] + rcx*wh1[67*256+t] + bh1[t];
        if (t < 64){
            g_offC[m*64+t] = ry*wc1[64*64+t] + rx*wc1[65*64+t]
                           + rcy*wc1[66*64+t] + rcx*wc1[67*64+t] + bc1[t];
            g_offL[m*64+t] = ry*wl1[64*64+t] + rx*wl1[65*64+t]
                           + rcy*wl1[66*64+t] + rcx*wl1[67*64+t] + bl1[t];
        }
    }
}

// ---------------- weight convert to fp16 [n][k] images ----------------
__global__ void wsplit_kernel(const float* __restrict__ wh2, const float* __restrict__ wh3)
{
    int idx = blockIdx.x*256 + threadIdx.x;       // 0..131071
    int layer = idx >> 16;
    int e = idx & 65535;
    int k = e >> 8, n = e & 255;
    const float* w = layer ? wh3 : wh2;
    float v = w[k*256 + n];
    if (layer) g_W3h[(uint32_t)n*256u + k] = __float2half(v);
    else       g_W2h[(uint32_t)n*256u + k] = __float2half(v);
}

// ---------------- 3x3 SAME conv; grid(96 rows, 4 oc-groups); 256 thr (R6 version) ----------------
template<int IC, bool RELU>
__global__ __launch_bounds__(256) void conv3x3_kernel(
    const float* __restrict__ in, const float* __restrict__ w,
    const float* __restrict__ bias, float* __restrict__ out)
{
    constexpr int CH = (IC < 16) ? IC : 16;
    __shared__ float sIn[CH][3][100];
    __shared__ float sW[16][CH][9];
    const int y   = blockIdx.x;
    const int ocg = blockIdx.y;
    const int tid = threadIdx.x;
    const int ol  = tid >> 4;
    const int oc  = ocg*16 + ol;
    const int x0  = (tid & 15) * 6;
    float acc[6];
#pragma unroll
    for (int j=0;j<6;j++) acc[j]=0.0f;

    for (int c0=0;c0<IC;c0+=CH){
        __syncthreads();
        for (int idx=tid; idx<CH*3*96; idx+=256){
            int ic = idx/288, rem = idx - ic*288, ry = rem/96, x = rem - ry*96;
            int yy = y + ry - 1;
            float v = 0.0f;
            if (yy>=0 && yy<96) v = in[(c0+ic)*HWLR + yy*96 + x];
            sIn[ic][ry][x+1] = v;
        }
        for (int idx=tid; idx<CH*3; idx+=256){
            int ic = idx/3, ry = idx-ic*3;
            sIn[ic][ry][0]=0.0f; sIn[ic][ry][97]=0.0f;
        }
        for (int idx=tid; idx<16*CH*9; idx+=256){
            int o = idx/(CH*9), rem = idx - o*(CH*9), ic = rem/9, t = rem - ic*9;
            sW[o][ic][t] = w[((ocg*16+o)*IC + c0+ic)*9 + t];
        }
        __syncthreads();
#pragma unroll 2
        for (int ic=0; ic<CH; ic++){
            float r0[8],r1[8],r2[8];
#pragma unroll
            for (int d=0;d<8;d++){
                r0[d]=sIn[ic][0][x0+d]; r1[d]=sIn[ic][1][x0+d]; r2[d]=sIn[ic][2][x0+d];
            }
            float w00=sW[ol][ic][0], w01=sW[ol][ic][1], w02=sW[ol][ic][2];
            float w10=sW[ol][ic][3], w11=sW[ol][ic][4], w12=sW[ol][ic][5];
            float w20=sW[ol][ic][6], w21=sW[ol][ic][7], w22=sW[ol][ic][8];
#pragma unroll
            for (int j=0;j<6;j++){
                acc[j] += w00*r0[j]+w01*r0[j+1]+w02*r0[j+2]
                        + w10*r1[j]+w11*r1[j+1]+w12*r1[j+2]
                        + w20*r2[j]+w21*r2[j+1]+w22*r2[j+2];
            }
        }
    }
    float b = __ldg(bias+oc);
#pragma unroll
    for (int j=0;j<6;j++){
        float v = acc[j]+b;
        if (RELU) v = fmaxf(v,0.0f);
        out[oc*HWLR + y*96 + x0 + j] = v;
    }
}

// ---------------- front GEMM: g_H[p][384] = feat[p][64] x [wc1|wl1|wh1] ----------------
__global__ __launch_bounds__(256) void front_kernel(
    const float* __restrict__ wc1, const float* __restrict__ wl1, const float* __restrict__ wh1)
{
    __shared__ float sF[64][25];
    __shared__ float sW[16][385];
    const int tid = threadIdx.x;
    const int P0  = blockIdx.x*24;
    const int txp = tid & 3;
    const int txc = tid >> 2;

    for (int i=tid; i<64*24; i+=256){
        int c = i/24, pl = i - c*24;
        sF[c][pl] = g_feat[c*HWLR + P0 + pl];
    }

    float acc[6][6];
#pragma unroll
    for (int i=0;i<6;i++)
#pragma unroll
        for (int j=0;j<6;j++) acc[i][j]=0.0f;

    for (int c0=0; c0<64; c0+=16){
        __syncthreads();
        for (int i=tid; i<16*384; i+=256){
            int cc = i/384, n = i - cc*384;
            int c = c0 + cc;
            float w;
            if (n < 64)        w = wc1[c*64 + n];
            else if (n < 128)  w = wl1[c*64 + (n-64)];
            else               w = wh1[c*256 + (n-128)];
            sW[cc][n] = w;
        }
        __syncthreads();
#pragma unroll
        for (int cc=0; cc<16; cc++){
            float f[6], w[6];
#pragma unroll
            for (int j=0;j<6;j++) f[j] = sF[c0+cc][txp*6+j];
#pragma unroll
            for (int i=0;i<6;i++) w[i] = sW[cc][txc*6+i];
#pragma unroll
            for (int i=0;i<6;i++)
#pragma unroll
                for (int j=0;j<6;j++) acc[i][j] += w[i]*f[j];
        }
    }
#pragma unroll
    for (int j=0;j<6;j++)
#pragma unroll
        for (int i=0;i<6;i++)
            g_H[(size_t)(P0 + txp*6 + j)*384 + txc*6 + i] = acc[i][j];
}

// ---------------- mlpB: classify/light/compact (no heavy work); 4 px per block ----------------
__global__ __launch_bounds__(256) void mlpB_kernel(
    const float* __restrict__ lr,
    const float* __restrict__ wc2, const float* __restrict__ bc2,
    const float* __restrict__ wl2, const float* __restrict__ bl2,
    float* __restrict__ out, int out_size)
{
    __shared__ float sHc[4][64];
    __shared__ float sHl[4][64];
    __shared__ float sPredL[4][16][3];
    __shared__ int sFlag[4][16];
    __shared__ int sInv[4][16];
    __shared__ int sMcount[4];
    __shared__ int sBase[4];

    const int tid = threadIdx.x;
    const int p0  = blockIdx.x*4;

    {
        int pp = tid>>6, c = tid&63;
        sHc[pp][c] = g_H[(size_t)(p0+pp)*384 + c];
        sHl[pp][c] = g_H[(size_t)(p0+pp)*384 + 64 + c];
    }
    __syncthreads();

    {
        int wid = tid>>5, lane = tid&31;
#pragma unroll
        for (int i=0;i<8;i++){
            int qq = wid*8 + i;
            int pp = qq>>4, m = qq&15;
            float l0=0,l1=0,q0=0,q1=0,q2=0;
#pragma unroll
            for (int hh=0;hh<2;hh++){
                int t = lane + hh*32;
                float hc = fmaxf(sHc[pp][t] + g_offC[m*64+t], 0.0f);
                l0 += hc*__ldg(&wc2[t*2+0]);
                l1 += hc*__ldg(&wc2[t*2+1]);
                float hl = fmaxf(sHl[pp][t] + g_offL[m*64+t], 0.0f);
                q0 += hl*__ldg(&wl2[t*3+0]);
                q1 += hl*__ldg(&wl2[t*3+1]);
                q2 += hl*__ldg(&wl2[t*3+2]);
            }
#pragma unroll
            for (int o=16;o>0;o>>=1){
                l0+=__shfl_xor_sync(0xffffffffu,l0,o);
                l1+=__shfl_xor_sync(0xffffffffu,l1,o);
                q0+=__shfl_xor_sync(0xffffffffu,q0,o);
                q1+=__shfl_xor_sync(0xffffffffu,q1,o);
                q2+=__shfl_xor_sync(0xffffffffu,q2,o);
            }
            if (lane==0){
                l0 += __ldg(&bc2[0]); l1 += __ldg(&bc2[1]);
                sFlag[pp][m] = (l1 > l0) ? 1 : 0;
                sPredL[pp][m][0] = q0 + __ldg(&bl2[0]);
                sPredL[pp][m][1] = q1 + __ldg(&bl2[1]);
                sPredL[pp][m][2] = q2 + __ldg(&bl2[2]);
            }
        }
    }
    __syncthreads();

    if (tid < 4){
        int c=0;
        for (int m=0;m<16;m++){
            sInv[tid][m] = -1;
            if (sFlag[tid][m]){ sInv[tid][m]=c; c++; }
        }
        sMcount[tid] = c;
    }
    __syncthreads();
    if (tid==0){
        int tot = sMcount[0]+sMcount[1]+sMcount[2]+sMcount[3];
        int b = tot ? atomicAdd(&g_cnt, tot) : 0;
        sBase[0]=b;
        sBase[1]=b+sMcount[0];
        sBase[2]=sBase[1]+sMcount[1];
        sBase[3]=sBase[2]+sMcount[2];
    }
    __syncthreads();

    if (tid < 64){
        int pp = tid>>4, mm = tid&15;
        int p = p0+pp, py = p/96, px = p - py*96;
        int r = py*4 + (mm>>2), s = px*4 + (mm&3);
        int q = r*HHR + s;
        g_flag[q] = sFlag[pp][mm];
        if (out_size >= 4*NQ) out[3*NQ + q] = (float)sFlag[pp][mm];
    }

    if (tid < 192){
        int pp = tid/48, r3 = tid - pp*48;
        int m = r3/3, j = r3 - m*3;
        int p = p0+pp, py = p/96, px = p - py*96;
        int r = py*4 + (m>>2), s = px*4 + (m&3);
        int q = r*HHR + s;
        float cy = -1.0f + (2.0f*(float)r + 1.0f)/384.0f;
        float cx = -1.0f + (2.0f*(float)s + 1.0f)/384.0f;
        float fy = fminf(fmaxf((cy+1.0f)*48.0f - 0.5f, 0.0f), 95.0f);
        float fx = fminf(fmaxf((cx+1.0f)*48.0f - 0.5f, 0.0f), 95.0f);
        float y0f = floorf(fy), x0f = floorf(fx);
        float wy = fy - y0f, wx = fx - x0f;
        int y0 = (int)y0f, x0 = (int)x0f;
        int y1 = min(y0+1,95), x1 = min(x0+1,95);
        const float* img = lr + j*HWLR;
        float v00=__ldg(&img[y0*96+x0]), v01=__ldg(&img[y0*96+x1]);
        float v10=__ldg(&img[y1*96+x0]), v11=__ldg(&img[y1*96+x1]);
        float resid = v00*(1.0f-wy)*(1.0f-wx) + v01*(1.0f-wy)*wx
                    + v10*wy*(1.0f-wx)       + v11*wy*wx;
        if (sFlag[pp][m]==0){
            g_pred[j*NQ + q] = sPredL[pp][m][j] + resid;
        } else {
            int slot = sBase[pp] + sInv[pp][m];
            g_resid[slot*3 + j] = resid;
            if (j==0) g_qidx[slot] = q;
        }
    }
}

// ---------------- B stage (fp16 hi only) via cp.async ----------------
__device__ __forceinline__ void stage_B(int tid, uint32_t bbase,
    const __half* __restrict__ Wh, int kc)
{
    for (int i=tid;i<1024;i+=256){
        int n=i>>2, c4=i&3;
        cp16(bbase + (uint32_t)n*(BPAD*2) + (uint32_t)c4*16, Wh + n*256 + kc*32 + c4*8);
    }
    asm volatile("cp.async.commit_group;");
}

// ---------------- GEMM: heavy layers 1(build)+2+3+4, 64-row tiles, fp16 2-product ----------------
__global__ __launch_bounds__(256, 2) void gemm_kernel(
    const float* __restrict__ bh2, const float* __restrict__ bh3,
    const float* __restrict__ wh4, const float* __restrict__ bh4)
{
    extern __shared__ unsigned char sm[];
    __shared__ float sB2[256], sB3[256], sBh4[4];
    __shared__ int sQ[TR];
    __shared__ int s_cnt;

    const int tid = threadIdx.x, wid = tid>>5, lane = tid&31;
    if (tid==0) s_cnt = g_cnt;
    __syncthreads();
    const int cnt  = s_cnt;
    const int base = blockIdx.x*TR;
    if (base >= cnt) return;
    const int valid = min(TR, cnt - base);

    sB2[tid]=__ldg(&bh2[tid]); sB3[tid]=__ldg(&bh3[tid]);
    if (tid<3) sBh4[tid]=__ldg(&bh4[tid]);
    if (tid < valid) sQ[tid] = g_qidx[base+tid];
    __syncthreads();

    // build A (h1 hi/lo fp16) directly from g_H + g_offH
    for (int i=0;i<valid;i++){
        int q = sQ[i];
        int r = q/HHR, s = q - r*HHR;
        int m = (r&3)*4 + (s&3);
        int p = (r>>2)*96 + (s>>2);
        float v = fmaxf(g_H[(size_t)p*384 + 128 + tid] + g_offH[m*256+tid], 0.0f);
        __half h = __float2half(v);
        __half l = __float2half(v - __half2float(h));
        *(unsigned short*)(sm + i*(KPAD*2) + tid*2)       = __half_as_ushort(h);
        *(unsigned short*)(sm + A_B + i*(KPAD*2) + tid*2) = __half_as_ushort(l);
    }

    const int wm = wid & 1;      // 2 row groups of 32
    const int wn = wid >> 1;     // 4 col groups of 64
    const uint32_t smA = smem_u32(sm);
    const uint32_t smB = smA + 2*A_B;

    float acc[64];
#pragma unroll
    for (int i=0;i<64;i++) acc[i]=0.0f;

    stage_B(tid, smB, g_W2h, 0);

    for (int idx=0; idx<16; idx++){
        if (idx < 15){
            int nx = idx+1;
            stage_B(tid, smB + (uint32_t)(nx&1)*B_COMP, (nx&8)?g_W3h:g_W2h, nx&7);
            asm volatile("cp.async.wait_group 1;");
        } else {
            asm volatile("cp.async.wait_group 0;");
        }
        __syncthreads();

        const int kc = idx & 7;
        const uint32_t bB = smB + (uint32_t)(idx&1)*B_COMP;
#pragma unroll
        for (int kk=0; kk<32; kk+=16){
            uint32_t ah[2][4], al[2][4];
#pragma unroll
            for (int mt=0; mt<2; mt++){
                int r = wm*32 + mt*16 + (lane&7) + ((lane>>3)&1)*8;
                int kcol = kc*32 + kk + (lane>>4)*8;
                uint32_t aAddr = smA + (uint32_t)(r*KPAD + kcol)*2u;
                ldsm4(ah[mt], aAddr);
                ldsm4(al[mt], aAddr + A_B);
            }
#pragma unroll
            for (int nt4=0; nt4<4; nt4++){
                int n = wn*64 + nt4*16 + (lane>>4)*8 + (lane&7);
                int kl = kk + ((lane>>3)&1)*8;
                uint32_t bh[4];
                ldsm4(bh, bB + (uint32_t)(n*BPAD + kl)*2u);
#pragma unroll
                for (int mt=0; mt<2; mt++){
#pragma unroll
                    for (int s2=0; s2<2; s2++){
                        const int ci = (mt*8 + nt4*2 + s2)*4;
                        mma_f16(acc[ci],acc[ci+1],acc[ci+2],acc[ci+3], ah[mt], bh[s2*2], bh[s2*2+1]);
                        mma_f16(acc[ci],acc[ci+1],acc[ci+2],acc[ci+3], al[mt], bh[s2*2], bh[s2*2+1]);
                    }
                }
            }
        }
        __syncthreads();

        if (idx == 7){
            // h2 = relu(D + bh2) -> fp16 hi/lo back into A smem
#pragma unroll
            for (int mt=0; mt<2; mt++){
#pragma unroll
                for (int nt=0; nt<8; nt++){
                    const int ci = (mt*8 + nt)*4;
                    int rowA = wm*32 + mt*16 + (lane>>2);
                    int col0 = wn*64 + nt*8 + (lane&3)*2;
                    uint32_t hi, lo;
                    split2h(fmaxf(acc[ci+0]+sB2[col0],0.0f), fmaxf(acc[ci+1]+sB2[col0+1],0.0f), hi, lo);
                    *(uint32_t*)(sm + rowA*(KPAD*2) + col0*2) = hi;
                    *(uint32_t*)(sm + A_B + rowA*(KPAD*2) + col0*2) = lo;
                    split2h(fmaxf(acc[ci+2]+sB2[col0],0.0f), fmaxf(acc[ci+3]+sB2[col0+1],0.0f), hi, lo);
                    *(uint32_t*)(sm + (rowA+8)*(KPAD*2) + col0*2) = hi;
                    *(uint32_t*)(sm + A_B + (rowA+8)*(KPAD*2) + col0*2) = lo;
                    acc[ci+0]=0.0f; acc[ci+1]=0.0f; acc[ci+2]=0.0f; acc[ci+3]=0.0f;
                }
            }
            __syncthreads();
        }
    }

    // h3 = relu(D + bh3) -> fp32 smem, then 256->3 reduction
    float* sF = (float*)sm;
#pragma unroll
    for (int mt=0; mt<2; mt++){
#pragma unroll
        for (int nt=0; nt<8; nt++){
            const int ci = (mt*8 + nt)*4;
            int rowA = wm*32 + mt*16 + (lane>>2);
            int col0 = wn*64 + nt*8 + (lane&3)*2;
            sF[rowA*FPAD + col0]       = fmaxf(acc[ci+0]+sB3[col0],   0.0f);
            sF[rowA*FPAD + col0+1]     = fmaxf(acc[ci+1]+sB3[col0+1], 0.0f);
            sF[(rowA+8)*FPAD + col0]   = fmaxf(acc[ci+2]+sB3[col0],   0.0f);
            sF[(rowA+8)*FPAD + col0+1] = fmaxf(acc[ci+3]+sB3[col0+1], 0.0f);
        }
    }
    __syncthreads();

    {
        int row = tid>>2, part = tid&3;
        const float4* rp = (const float4*)(sF + row*FPAD + part*64);
        float a0=0,a1=0,a2=0;
#pragma unroll
        for (int j=0;j<16;j++){
            float4 v = rp[j];
            int cb = part*64 + j*4;
            a0 += v.x*__ldg(&wh4[cb*3+0]) + v.y*__ldg(&wh4[(cb+1)*3+0]) + v.z*__ldg(&wh4[(cb+2)*3+0]) + v.w*__ldg(&wh4[(cb+3)*3+0]);
            a1 += v.x*__ldg(&wh4[cb*3+1]) + v.y*__ldg(&wh4[(cb+1)*3+1]) + v.z*__ldg(&wh4[(cb+2)*3+1]) + v.w*__ldg(&wh4[(cb+3)*3+1]);
            a2 += v.x*__ldg(&wh4[cb*3+2]) + v.y*__ldg(&wh4[(cb+1)*3+2]) + v.z*__ldg(&wh4[(cb+2)*3+2]) + v.w*__ldg(&wh4[(cb+3)*3+2]);
        }
#pragma unroll
        for (int o=1;o<4;o<<=1){
            a0 += __shfl_xor_sync(0xffffffffu, a0, o);
            a1 += __shfl_xor_sync(0xffffffffu, a1, o);
            a2 += __shfl_xor_sync(0xffffffffu, a2, o);
        }
        if (part==0 && row < valid){
            int slot = base + row;
            int q = sQ[row];
            g_pred[       q] = a0 + sBh4[0] + g_resid[slot*3+0];
            g_pred[  NQ + q] = a1 + sBh4[1] + g_resid[slot*3+1];
            g_pred[2*NQ + q] = a2 + sBh4[2] + g_resid[slot*3+2];
        }
    }
}

// ---------------- refinement ----------------
__global__ __launch_bounds__(256) void refine_kernel(float* __restrict__ out)
{
    int q = blockIdx.x*256 + threadIdx.x;
    if (q >= NQ) return;
    int r = q/HHR, s = q - r*HHR;
    float p0 = g_pred[q], p1 = g_pred[NQ+q], p2 = g_pred[2*NQ+q];
    if (r>0 && r<HHR-1 && s>0 && s<HHR-1 && g_flag[q]==0){
        int fs = 0;
#pragma unroll
        for (int dy=-1;dy<=1;dy++)
#pragma unroll
            for (int dx=-1;dx<=1;dx++)
                fs += g_flag[q + dy*HHR + dx];
        if (fs > 0){
            float s0=0,s1=0,s2=0;
#pragma unroll
            for (int dy=-1;dy<=1;dy++)
#pragma unroll
                for (int dx=-1;dx<=1;dx++){
                    int qq = q + dy*HHR + dx;
                    s0 += g_pred[qq];
                    s1 += g_pred[NQ+qq];
                    s2 += g_pred[2*NQ+qq];
                }
            p0 = s0/9.0f; p1 = s1/9.0f; p2 = s2/9.0f;
        }
    }
    out[q*3+0] = p0;
    out[q*3+1] = p1;
    out[q*3+2] = p2;
}

// ---------------- launch ----------------
extern "C" void kernel_launch(void* const* d_in, const int* in_sizes, int n_in,
                              void* d_out, int out_size)
{
    (void)in_sizes; (void)n_in;
    const float* lr  =(const float*)d_in[0];
    const float* cell=(const float*)d_in[2];
    const float* ew1 =(const float*)d_in[3];
    const float* eb1 =(const float*)d_in[4];
    const float* ew2 =(const float*)d_in[5];
    const float* eb2 =(const float*)d_in[6];
    const float* ew3 =(const float*)d_in[7];
    const float* eb3 =(const float*)d_in[8];
    const float* wh1 =(const float*)d_in[9];
    const float* bh1 =(const float*)d_in[10];
    const float* wh2 =(const float*)d_in[11];
    const float* bh2 =(const float*)d_in[12];
    const float* wh3 =(const float*)d_in[13];
    const float* bh3 =(const float*)d_in[14];
    const float* wh4 =(const float*)d_in[15];
    const float* bh4 =(const float*)d_in[16];
    const float* wl1 =(const float*)d_in[17];
    const float* bl1 =(const float*)d_in[18];
    const float* wl2 =(const float*)d_in[19];
    const float* bl2 =(const float*)d_in[20];
    const float* wc1 =(const float*)d_in[21];
    const float* bc1 =(const float*)d_in[22];
    const float* wc2 =(const float*)d_in[23];
    const float* bc2 =(const float*)d_in[24];
    float* out = (float*)d_out;

    float *b1, *b2, *feat;
    cudaGetSymbolAddress((void**)&b1,   g_b1);
    cudaGetSymbolAddress((void**)&b2,   g_b2);
    cudaGetSymbolAddress((void**)&feat, g_feat);

    cudaFuncSetAttribute(gemm_kernel, cudaFuncAttributeMaxDynamicSharedMemorySize, DSM2);

    precompute_kernel<<<1,256>>>(wh1,bh1,wc1,bc1,wl1,bl1,cell);
    wsplit_kernel<<<512,256>>>(wh2, wh3);
    conv3x3_kernel<3 ,true ><<<dim3(96,4),256>>>(lr, ew1, eb1, b1);
    conv3x3_kernel<64,true ><<<dim3(96,4),256>>>(b1, ew2, eb2, b2);
    conv3x3_kernel<64,false><<<dim3(96,4),256>>>(b2, ew3, eb3, feat);
    front_kernel<<<384,256>>>(wc1, wl1, wh1);
    mlpB_kernel<<<2304,256>>>(lr, wc2, bc2, wl2, bl2, out, out_size);
    gemm_kernel<<<NT2,256,DSM2>>>(bh2, bh3, wh4, bh4);
    refine_kernel<<<(NQ+255)/256,256>>>(out);
}